// round 10
// baseline (speedup 1.0000x reference)
#include <cuda_runtime.h>
#include <cuda_bf16.h>
#include <math.h>
#include <stdint.h>

// Problem constants
#define Bb   2
#define Ss   1024
#define Dd   1024
#define Ee   2048
#define Nn   16
#define Rr   64
#define BSr  (Bb * Ss)          // 2048 rows
#define DBCW (Rr + 2 * Nn)      // 96
#define THREED (3 * Dd)         // 3072
#define KSPLIT 8
#define SCH  64                 // scan chunk (steps per SMEM stage)
#define NCH  (Ss / SCH)         // 16 chunks

// ---------------- scratch (device globals; no allocation in kernel_launch) ----
__device__ float g_ada  [Bb * THREED];
__device__ float g_skip [BSr * Dd];
__device__ float g_xn   [BSr * Dd];
__device__ float g_mzx  [BSr * 2 * Ee];      // mz | mx  (ld = 4096)
__device__ float g_z12  [BSr * 2 * Ee];      // z1 | z2  (ld = 4096)
__device__ float g_dbc1 [BSr * DBCW];
__device__ float g_dbc2 [BSr * DBCW];
__device__ float g_del1 [BSr * Ee];
__device__ float g_del2 [BSr * Ee];
__device__ float g_gg1  [BSr * Ee];
__device__ float g_gg2  [BSr * Ee];
__device__ float g_acmb [BSr * Ee];
__device__ float g_part [2 * KSPLIT * BSr * DBCW];
// pre-rounded (tf32) weights / concat biases
__device__ float g_wzx  [2 * Ee * Dd];       // [Wz ; Wx] rounded
__device__ float g_wc12 [2 * Ee * Ee];       // [Wc1 ; Wc2] rounded
__device__ float g_wdbc1[DBCW * Ee];
__device__ float g_wdbc2[DBCW * Ee];
__device__ float g_wdt1 [Ee * Rr];
__device__ float g_wdt2 [Ee * Rr];
__device__ float g_wf   [Dd * Ee];
__device__ float g_bzx  [2 * Ee];            // [bz ; bx]
__device__ float g_bc12 [2 * Ee];            // [bc1 ; bc2]

// ---------------- helpers -----------------------------------------------------
__device__ __forceinline__ float siluf(float v) { return v / (1.0f + __expf(-v)); }
__device__ __forceinline__ float softplusf(float v) {
    return (v > 20.0f) ? v : log1pf(__expf(v));
}
__device__ __forceinline__ uint32_t f2tf32(float f) {
    uint32_t u;
    asm("cvt.rna.tf32.f32 %0, %1;" : "=r"(u) : "f"(f));
    return u;
}
__device__ __forceinline__ float roundtf(float f) {
    return __uint_as_float(f2tf32(f));
}
__device__ __forceinline__ void mma_tf32(float* c, const uint32_t* a, const uint32_t* b) {
    asm volatile(
        "mma.sync.aligned.m16n8k8.row.col.f32.tf32.tf32.f32 "
        "{%0,%1,%2,%3},{%4,%5,%6,%7},{%8,%9},{%0,%1,%2,%3};"
        : "+f"(c[0]), "+f"(c[1]), "+f"(c[2]), "+f"(c[3])
        : "r"(a[0]), "r"(a[1]), "r"(a[2]), "r"(a[3]), "r"(b[0]), "r"(b[1]));
}
#define CP16(dst, src, sz) \
    asm volatile("cp.async.cg.shared.global [%0], [%1], 16, %2;" \
                 :: "r"(dst), "l"(src), "r"(sz))
#define CP16F(dst, src) \
    asm volatile("cp.async.cg.shared.global [%0], [%1], 16;" \
                 :: "r"(dst), "l"(src))

__device__ __forceinline__ float blockReduceSum(float v, float* sh) {
    int lane = threadIdx.x & 31, wid = threadIdx.x >> 5;
#pragma unroll
    for (int o = 16; o; o >>= 1) v += __shfl_xor_sync(0xffffffffu, v, o);
    __syncthreads();
    if (lane == 0) sh[wid] = v;
    __syncthreads();
    if (wid == 0) {
        v = (lane < 8) ? sh[lane] : 0.0f;
#pragma unroll
        for (int o = 4; o; o >>= 1) v += __shfl_xor_sync(0xffffffffu, v, o);
        if (lane == 0) sh[0] = v;
    }
    __syncthreads();
    return sh[0];
}

// ---------------- fused weight round + bias concat (13 segments) ----------------
#define NSEG 13
struct RoundJobs {
    const float4* src[NSEG];
    float4*       dst[NSEG];
    int           off[NSEG + 1];
    int           rnd[NSEG];
};

__global__ void round_all_kernel(RoundJobs jb, int total4) {
    int i = blockIdx.x * blockDim.x + threadIdx.x;
    if (i >= total4) return;
    int s = 0;
#pragma unroll
    for (int k = 1; k < NSEG; k++) if (i >= jb.off[k]) s = k;
    int j = i - jb.off[s];
    float4 v = jb.src[s][j];
    if (jb.rnd[s]) {
        v.x = roundtf(v.x); v.y = roundtf(v.y);
        v.z = roundtf(v.z); v.w = roundtf(v.w);
    }
    jb.dst[s][j] = v;
}

// ---------------- tf32 tensor-core GEMM (3-stage, single sync/tile) -------------
// C[M,N] = A[M,K] * W[N,K]^T (+bias, +epi). Tile 128x128x32, 256 threads,
// 8 warps (2x4), warp tile 64x32, mma m16n8k8 tf32. 3-stage cp.async pipeline,
// ONE __syncthreads per k-tile (issue-after-sync ordering), XOR-swizzled SMEM.
// epi: 0 none, 1 softplus, 3 fused ViM final (out = x + gate*(acc+bias+skip)).
// nRound: columns [0,nRound) rna-rounded on store.
// Batching: blockIdx.z in [0, splitK * nBranch); branch = z / splitK selects
// (A2,W2,bias2,C2). Output at C + z*partStride (bias only when splitK == 1).
__global__ __launch_bounds__(256, 2) void gemm_tf32(
    const float* __restrict__ A_, int lda,
    const float* __restrict__ W_, int ldb,
    const float* __restrict__ bias_,
    float* __restrict__ C_, int ldc,
    int M, int N, int K, int epi, int nRound, int splitK, int partStride,
    const float* A2, const float* W2, const float* bias2, float* C2,
    const float* xP, const float* skipP, const float* adaP)
{
    extern __shared__ float smf[];
    float* As = smf;             // [3][128*32]
    float* Bs = smf + 12288;     // [3][128*32]

    const float* A = A_;
    const float* W = W_;
    const float* bias = bias_;
    float* C = C_;

    const int bz = blockIdx.z;
    const int br = bz / splitK;
    const int kz = bz % splitK;
    if (br == 1) { A = A2; W = W2; bias = bias2; if (C2) C = C2; }

    const int tid  = threadIdx.x;
    const int wid  = tid >> 5, lane = tid & 31;
    const int wm   = wid >> 2, wn = wid & 3;
    const int grp  = lane >> 2, tig = lane & 3;
    const int bm   = blockIdx.y * 128, bn = blockIdx.x * 128;
    const int klen   = K / splitK;
    const int kstart = kz * klen;
    const int ntile  = klen >> 5;

    float acc[4][4][4];
#pragma unroll
    for (int i = 0; i < 4; i++)
#pragma unroll
        for (int j = 0; j < 4; j++)
#pragma unroll
            for (int r = 0; r < 4; r++) acc[i][j][r] = 0.0f;

    uint32_t aSm[4], bSm[4], bSz[4];
    const float* aP[4];
    const float* bP[4];
    const uint32_t sA = (uint32_t)__cvta_generic_to_shared(As);
    const uint32_t sB = (uint32_t)__cvta_generic_to_shared(Bs);
#pragma unroll
    for (int i = 0; i < 4; i++) {
        int f = tid + i * 256;
        int m = f >> 3, kq = (f & 7) * 4;
        int col = kq ^ ((m & 7) << 2);
        aSm[i] = sA + (uint32_t)(m * 32 + col) * 4u;
        bSm[i] = sB + (uint32_t)(m * 32 + col) * 4u;
        aP[i]  = A + (size_t)(bm + m) * lda + kstart + kq;
        int brow = bn + m;
        bSz[i] = (brow < N) ? 16u : 0u;
        if (brow >= N) brow = N - 1;
        bP[i]  = W + (size_t)brow * ldb + kstart + kq;
    }

    // prologue: stages 0 and 1
#pragma unroll
    for (int st = 0; st < 2; st++) {
        if (st < ntile) {
            const uint32_t so = (uint32_t)st * 16384u;
#pragma unroll
            for (int i = 0; i < 4; i++) {
                CP16(aSm[i] + so, aP[i], 16u);
                CP16(bSm[i] + so, bP[i], bSz[i]);
                aP[i] += 32; bP[i] += 32;
            }
            asm volatile("cp.async.commit_group;");
        }
    }

    const int swz = grp << 2;

#pragma unroll 3
    for (int t = 0; t < ntile; t++) {
        if (t + 1 < ntile) {
            asm volatile("cp.async.wait_group 1;");
        } else {
            asm volatile("cp.async.wait_group 0;");
        }
        __syncthreads();

        // issue stage t+2 AFTER the barrier: its buffer ((t+2)%3 == (t-1)%3)
        // was only read in compute(t-1), which every warp has finished.
        if (t + 2 < ntile) {
            const int st = (t + 2) % 3;
            const uint32_t so = (uint32_t)st * 16384u;
#pragma unroll
            for (int i = 0; i < 4; i++) {
                CP16(aSm[i] + so, aP[i], 16u);
                CP16(bSm[i] + so, bP[i], bSz[i]);
                aP[i] += 32; bP[i] += 32;
            }
            asm volatile("cp.async.commit_group;");
        }

        const int buf = (t % 3) * 4096;
#pragma unroll
        for (int ks = 0; ks < 4; ks++) {
            const int kb = ks * 8;
            const int c0 = (kb + tig) ^ swz;
            const int c1 = (kb + tig + 4) ^ swz;
            uint32_t af[4][4], bf[4][2];
#pragma unroll
            for (int mt = 0; mt < 4; mt++) {
                int r0 = (wm * 64 + mt * 16 + grp) * 32;
                af[mt][0] = __float_as_uint(As[buf + r0 + c0]);
                af[mt][1] = __float_as_uint(As[buf + r0 + 256 + c0]);
                af[mt][2] = __float_as_uint(As[buf + r0 + c1]);
                af[mt][3] = __float_as_uint(As[buf + r0 + 256 + c1]);
            }
#pragma unroll
            for (int nt = 0; nt < 4; nt++) {
                int r0 = (wn * 32 + nt * 8 + grp) * 32;
                bf[nt][0] = __float_as_uint(Bs[buf + r0 + c0]);
                bf[nt][1] = __float_as_uint(Bs[buf + r0 + c1]);
            }
#pragma unroll
            for (int mt = 0; mt < 4; mt++)
#pragma unroll
                for (int nt = 0; nt < 4; nt++)
                    mma_tf32(acc[mt][nt], af[mt], bf[nt]);
        }
    }

    float* Cp = C + (size_t)bz * partStride;
    const bool doBias = (bias != nullptr) && (splitK == 1);
#pragma unroll
    for (int mt = 0; mt < 4; mt++) {
#pragma unroll
        for (int nt = 0; nt < 4; nt++) {
            int row = bm + wm * 64 + mt * 16 + grp;
            int col = bn + wn * 32 + nt * 8 + tig * 2;
            if (col >= N) continue;
            float b0 = doBias ? __ldg(bias + col) : 0.0f;
            float b1 = doBias ? __ldg(bias + col + 1) : 0.0f;
            float v0 = acc[mt][nt][0] + b0, v1 = acc[mt][nt][1] + b1;
            float v2 = acc[mt][nt][2] + b0, v3 = acc[mt][nt][3] + b1;
            if (epi == 1) {
                v0 = softplusf(v0); v1 = softplusf(v1);
                v2 = softplusf(v2); v3 = softplusf(v3);
            } else if (epi == 3) {
                // out = x + gate * (acc + bias + skip); rows within one tile share b
                int bb = row >> 10;
                float g0 = __ldg(adaP + bb * THREED + 2 * Dd + col);
                float g1 = __ldg(adaP + bb * THREED + 2 * Dd + col + 1);
                size_t i0 = (size_t)row * Dd + col;
                size_t i1 = (size_t)(row + 8) * Dd + col;
                v0 = __ldg(xP + i0)     + g0 * (v0 + __ldg(skipP + i0));
                v1 = __ldg(xP + i0 + 1) + g1 * (v1 + __ldg(skipP + i0 + 1));
                v2 = __ldg(xP + i1)     + g0 * (v2 + __ldg(skipP + i1));
                v3 = __ldg(xP + i1 + 1) + g1 * (v3 + __ldg(skipP + i1 + 1));
            }
            if (col < nRound) {
                v0 = roundtf(v0); v1 = roundtf(v1);
                v2 = roundtf(v2); v3 = roundtf(v3);
            }
            float2 lo = make_float2(v0, v1), hi = make_float2(v2, v3);
            *(float2*)&Cp[(size_t)row * ldc + col] = lo;
            *(float2*)&Cp[(size_t)(row + 8) * ldc + col] = hi;
        }
    }
}

// ---------------- split-K reduction for both branches (rounds output) ------------
__global__ void reduce_splitk2(const float* __restrict__ part,
                               float* __restrict__ out1,
                               float* __restrict__ out2, int n)
{
    int i = blockIdx.x * blockDim.x + threadIdx.x;
    if (i < 2 * n) {
        int br = (i >= n);
        int j  = i - br * n;
        const float* p = part + (size_t)(br * KSPLIT) * n + j;
        float s = 0.0f;
#pragma unroll
        for (int z = 0; z < KSPLIT; z++) s += p[(size_t)z * n];
        float v = roundtf(s);
        if (br) out2[j] = v; else out1[j] = v;
    }
}

// ---------------- ada: one warp computes both batch outputs ----------------------
__global__ __launch_bounds__(256) void ada_kernel(
    const float* __restrict__ c, const float* __restrict__ Wada,
    const float* __restrict__ bada, float* __restrict__ ada)
{
    int w    = (blockIdx.x * blockDim.x + threadIdx.x) >> 5;   // 0..3071
    int lane = threadIdx.x & 31;

    const float4* wp  = (const float4*)(Wada + (size_t)w * 2 * Dd);
    const float4* c0p = (const float4*)c;
    const float4* c1p = (const float4*)(c + 2 * Dd);
    float s0 = 0.0f, s1 = 0.0f;
#pragma unroll
    for (int it = 0; it < 16; it++) {
        float4 wv = __ldg(&wp[lane + it * 32]);
        float4 a0 = __ldg(&c0p[lane + it * 32]);
        float4 a1 = __ldg(&c1p[lane + it * 32]);
        s0 += siluf(a0.x) * wv.x + siluf(a0.y) * wv.y
            + siluf(a0.z) * wv.z + siluf(a0.w) * wv.w;
        s1 += siluf(a1.x) * wv.x + siluf(a1.y) * wv.y
            + siluf(a1.z) * wv.z + siluf(a1.w) * wv.w;
    }
#pragma unroll
    for (int off = 16; off; off >>= 1) {
        s0 += __shfl_xor_sync(0xffffffffu, s0, off);
        s1 += __shfl_xor_sync(0xffffffffu, s1, off);
    }
    if (lane == 0) {
        float bv = __ldg(bada + w);
        ada[w] = s0 + bv;
        ada[THREED + w] = s1 + bv;
    }
}

// ---------------- fused LN1 + modulate(+store skip) + LN2 (xn rounded) -----------
__global__ __launch_bounds__(256) void ln_mod_kernel(
    const float* __restrict__ x,
    const float* __restrict__ g1, const float* __restrict__ b1,
    const float* __restrict__ g2, const float* __restrict__ b2,
    const float* __restrict__ ada,
    float* __restrict__ skip, float* __restrict__ xn)
{
    __shared__ float sh[8];
    const int row = blockIdx.x;
    const int b = row >> 10;
    const float* xr = x + (size_t)row * Dd;

    float v[4];
#pragma unroll
    for (int j = 0; j < 4; j++) v[j] = xr[threadIdx.x + j * 256];

    float s1 = 0.0f, s2 = 0.0f;
#pragma unroll
    for (int j = 0; j < 4; j++) { s1 += v[j]; s2 += v[j] * v[j]; }
    s1 = blockReduceSum(s1, sh);
    s2 = blockReduceSum(s2, sh);
    float m  = s1 * (1.0f / Dd);
    float rs = rsqrtf(s2 * (1.0f / Dd) - m * m + 1e-5f);

    float t[4];
    s1 = 0.0f; s2 = 0.0f;
#pragma unroll
    for (int j = 0; j < 4; j++) {
        int d = threadIdx.x + j * 256;
        float tt = (v[j] - m) * rs * g1[d] + b1[d];
        tt = tt * (1.0f + ada[b * THREED + Dd + d]) + ada[b * THREED + d];
        t[j] = tt;
        skip[(size_t)row * Dd + d] = tt;
        s1 += tt; s2 += tt * tt;
    }
    s1 = blockReduceSum(s1, sh);
    s2 = blockReduceSum(s2, sh);
    float m2  = s1 * (1.0f / Dd);
    float rs2 = rsqrtf(s2 * (1.0f / Dd) - m2 * m2 + 1e-5f);

#pragma unroll
    for (int j = 0; j < 4; j++) {
        int d = threadIdx.x + j * 256;
        xn[(size_t)row * Dd + d] = roundtf((t[j] - m2) * rs2 * g2[d] + b2[d]);
    }
}

// ---------------- SMEM-staged selective scan -------------------------------------
__global__ __launch_bounds__(256) void scan_smem_kernel(
    const float* __restrict__ de1, const float* __restrict__ de2,
    const float* __restrict__ z12, int ldz,
    const float* __restrict__ dbc1, const float* __restrict__ dbc2,
    const float* __restrict__ Alog1, const float* __restrict__ Alog2,
    const float* __restrict__ Dp1, const float* __restrict__ Dp2,
    float* __restrict__ gg1, float* __restrict__ gg2)
{
    __shared__ float deS[2][SCH][16];
    __shared__ float zS [2][SCH][16];
    __shared__ float bcS[2][SCH][32];
    __shared__ float ggS[SCH][16];

    const int tid = threadIdx.x;
    const int u   = tid >> 4;
    const int n   = tid & 15;

    const int bx = blockIdx.x;         // 0..511
    const int et = bx & 127;
    const int b  = (bx >> 7) & 1;
    const int br = bx >> 8;
    const int e0 = et * 16;

    const float* de   = br ? de2  : de1;
    const float* z    = z12 + (br ? Ee : 0);
    const float* dbc  = br ? dbc2 : dbc1;
    const float* Alog = br ? Alog2 : Alog1;
    const float* Dp   = br ? Dp2  : Dp1;
    float*       gg   = br ? gg2  : gg1;

    const int e = e0 + u;
    const float A_n  = -__expf(Alog[e * Nn + n]);
    const float Dp_e = Dp[e];

    const size_t rowBase = (size_t)b * Ss;

    uint32_t deSm = (uint32_t)__cvta_generic_to_shared(&deS[0][0][0]);
    uint32_t zSm  = (uint32_t)__cvta_generic_to_shared(&zS[0][0][0]);
    uint32_t bcSm = (uint32_t)__cvta_generic_to_shared(&bcS[0][0][0]);

    const int lr  = tid >> 2;
    const int lp  = (tid & 3) * 4;
    const int br0 = (tid * 2) >> 3;
    const int bp0 = ((tid * 2) & 7) * 4;
    const int br1 = (tid * 2 + 1) >> 3;
    const int bp1 = ((tid * 2 + 1) & 7) * 4;

    auto loadChunk = [&](int c, int buf) {
        int s = br ? (Ss - 1 - (c * SCH + lr)) : (c * SCH + lr);
        const float* gd = de + (rowBase + s) * Ee + e0 + lp;
        const float* gz = z  + (rowBase + s) * (size_t)ldz + e0 + lp;
        CP16F(deSm + (uint32_t)((buf * SCH + lr) * 16 + lp) * 4u, gd);
        CP16F(zSm  + (uint32_t)((buf * SCH + lr) * 16 + lp) * 4u, gz);
        int s0 = br ? (Ss - 1 - (c * SCH + br0)) : (c * SCH + br0);
        int s1b = br ? (Ss - 1 - (c * SCH + br1)) : (c * SCH + br1);
        const float* g0 = dbc + (rowBase + s0) * DBCW + Rr + bp0;
        const float* g1 = dbc + (rowBase + s1b) * DBCW + Rr + bp1;
        CP16F(bcSm + (uint32_t)((buf * SCH + br0) * 32 + bp0) * 4u, g0);
        CP16F(bcSm + (uint32_t)((buf * SCH + br1) * 32 + bp1) * 4u, g1);
    };

    loadChunk(0, 0);
    asm volatile("cp.async.commit_group;");

    float h = 0.0f;

    for (int c = 0; c < NCH; c++) {
        if (c + 1 < NCH) {
            loadChunk(c + 1, (c + 1) & 1);
            asm volatile("cp.async.commit_group;");
            asm volatile("cp.async.wait_group 1;");
        } else {
            asm volatile("cp.async.wait_group 0;");
        }
        __syncthreads();

        const int buf = c & 1;
#pragma unroll 8
        for (int cs = 0; cs < SCH; cs++) {
            float dlt = deS[buf][cs][u];
            float uu  = zS[buf][cs][u];
            float Bv  = bcS[buf][cs][n];
            float Cv  = bcS[buf][cs][16 + n];

            h = __expf(dlt * A_n) * h + dlt * Bv * uu;
            float y = h * Cv;
            y += __shfl_xor_sync(0xffffffffu, y, 8);
            y += __shfl_xor_sync(0xffffffffu, y, 4);
            y += __shfl_xor_sync(0xffffffffu, y, 2);
            y += __shfl_xor_sync(0xffffffffu, y, 1);
            if (n == 0) ggS[cs][u] = y + uu * Dp_e;
        }
        __syncthreads();

        {
            int r = tid >> 2, p = (tid & 3) * 4;
            int s = br ? (Ss - 1 - (c * SCH + r)) : (c * SCH + r);
            *(float4*)&gg[(rowBase + s) * Ee + e0 + p] = *(float4*)&ggS[r][p];
        }
    }
}

// ---------------- acmb = silu(mx) * (gg1 + gg2), rounded --------------------------
__global__ void combine_kernel(const float4* __restrict__ mzx,
                               const float4* __restrict__ gg1,
                               const float4* __restrict__ gg2,
                               float4* __restrict__ a, int n4)
{
    int i = blockIdx.x * blockDim.x + threadIdx.x;
    if (i < n4) {
        int row  = i >> 9;              // / (Ee/4)
        int col4 = i & 511;
        float4 m = mzx[row * 1024 + 512 + col4];   // mx half (ld=4096 floats)
        float4 p = gg1[i], q = gg2[i], r;
        r.x = roundtf(siluf(m.x) * (p.x + q.x));
        r.y = roundtf(siluf(m.y) * (p.y + q.y));
        r.z = roundtf(siluf(m.z) * (p.z + q.z));
        r.w = roundtf(siluf(m.w) * (p.w + q.w));
        a[i] = r;
    }
}

// ---------------- host launcher ----------------------------------------------------
extern "C" void kernel_launch(void* const* d_in, const int* in_sizes, int n_in,
                              void* d_out, int out_size)
{
    const float* x     = (const float*)d_in[0];
    const float* c     = (const float*)d_in[1];
    const float* n1g   = (const float*)d_in[3];
    const float* n1b   = (const float*)d_in[4];
    const float* n2g   = (const float*)d_in[5];
    const float* n2b   = (const float*)d_in[6];
    const float* Wx    = (const float*)d_in[7];
    const float* bx    = (const float*)d_in[8];
    const float* Wz    = (const float*)d_in[9];
    const float* bz    = (const float*)d_in[10];
    const float* Wf    = (const float*)d_in[11];
    const float* bf    = (const float*)d_in[12];
    const float* Wada  = (const float*)d_in[13];
    const float* bada  = (const float*)d_in[14];
    const float* Wc1   = (const float*)d_in[15];
    const float* bc1   = (const float*)d_in[16];
    const float* Wc2   = (const float*)d_in[17];
    const float* bc2   = (const float*)d_in[18];
    const float* Wdbc1 = (const float*)d_in[19];
    const float* Wdt1  = (const float*)d_in[20];
    const float* bdt1  = (const float*)d_in[21];
    const float* Alog1 = (const float*)d_in[22];
    const float* Dp1   = (const float*)d_in[23];
    const float* Wdbc2 = (const float*)d_in[24];
    const float* Wdt2  = (const float*)d_in[25];
    const float* bdt2  = (const float*)d_in[26];
    const float* Alog2 = (const float*)d_in[27];
    const float* Dp2   = (const float*)d_in[28];
    float* out = (float*)d_out;

    float *ada, *skip, *xn, *mzx, *z12, *dbc1, *dbc2;
    float *de1, *de2, *gg1, *gg2, *acmb, *part;
    float *wzx, *wc12, *wdbc1, *wdbc2, *wdt1, *wdt2, *wf, *bzx, *bc12;
    cudaGetSymbolAddress((void**)&ada,  g_ada);
    cudaGetSymbolAddress((void**)&skip, g_skip);
    cudaGetSymbolAddress((void**)&xn,   g_xn);
    cudaGetSymbolAddress((void**)&mzx,  g_mzx);
    cudaGetSymbolAddress((void**)&z12,  g_z12);
    cudaGetSymbolAddress((void**)&dbc1, g_dbc1);
    cudaGetSymbolAddress((void**)&dbc2, g_dbc2);
    cudaGetSymbolAddress((void**)&de1,  g_del1);
    cudaGetSymbolAddress((void**)&de2,  g_del2);
    cudaGetSymbolAddress((void**)&gg1,  g_gg1);
    cudaGetSymbolAddress((void**)&gg2,  g_gg2);
    cudaGetSymbolAddress((void**)&acmb, g_acmb);
    cudaGetSymbolAddress((void**)&part, g_part);
    cudaGetSymbolAddress((void**)&wzx,   g_wzx);
    cudaGetSymbolAddress((void**)&wc12,  g_wc12);
    cudaGetSymbolAddress((void**)&wdbc1, g_wdbc1);
    cudaGetSymbolAddress((void**)&wdbc2, g_wdbc2);
    cudaGetSymbolAddress((void**)&wdt1,  g_wdt1);
    cudaGetSymbolAddress((void**)&wdt2,  g_wdt2);
    cudaGetSymbolAddress((void**)&wf,    g_wf);
    cudaGetSymbolAddress((void**)&bzx,   g_bzx);
    cudaGetSymbolAddress((void**)&bc12,  g_bc12);

    const int SMEM = 98304;   // 3-stage pipeline: 2 x 3 x 16KB
    cudaFuncSetAttribute(gemm_tf32, cudaFuncAttributeMaxDynamicSharedMemorySize, SMEM);

    // 1. fused weight round + bias concat (one launch)
    {
        RoundJobs jb;
        const float* srcs[NSEG] = { Wz, Wx, Wc1, Wc2, Wdbc1, Wdbc2, Wdt1, Wdt2, Wf,
                                    bz, bx, bc1, bc2 };
        float* dsts[NSEG] = { wzx, wzx + (size_t)Ee * Dd,
                              wc12, wc12 + (size_t)Ee * Ee,
                              wdbc1, wdbc2, wdt1, wdt2, wf,
                              bzx, bzx + Ee, bc12, bc12 + Ee };
        int sizes4[NSEG] = { Ee * Dd / 4, Ee * Dd / 4, Ee * Ee / 4, Ee * Ee / 4,
                             DBCW * Ee / 4, DBCW * Ee / 4, Ee * Rr / 4, Ee * Rr / 4,
                             Dd * Ee / 4, Ee / 4, Ee / 4, Ee / 4, Ee / 4 };
        int rnds[NSEG] = { 1,1,1,1,1,1,1,1,1, 0,0,0,0 };
        int off = 0;
        for (int s = 0; s < NSEG; s++) {
            jb.src[s] = (const float4*)srcs[s];
            jb.dst[s] = (float4*)dsts[s];
            jb.off[s] = off;
            jb.rnd[s] = rnds[s];
            off += sizes4[s];
        }
        jb.off[NSEG] = off;
        round_all_kernel<<<(off + 255) / 256, 256>>>(jb, off);
    }

    // 2. ada = silu(c) @ Wada^T + bada  (one warp -> both batch rows)
    ada_kernel<<<384, 256>>>(c, Wada, bada, ada);

    // 3. LN1 + modulate (-> skip) + LN2 (-> xn, rounded)
    ln_mod_kernel<<<BSr, 256>>>(x, n1g, n1b, n2g, n2b, ada, skip, xn);

    // 4. merged mz|mx  [2048, 4096] K=1024
    gemm_tf32<<<dim3(2 * Ee / 128, BSr / 128, 1), 256, SMEM>>>(
        xn, Dd, wzx, Dd, bzx, mzx, 2 * Ee, BSr, 2 * Ee, Dd, 0, Ee, 1, 0,
        nullptr, nullptr, nullptr, nullptr, nullptr, nullptr, nullptr);

    // 5. merged z1|z2  [2048, 4096] K=2048 (A = mz half of mzx, lda=4096)
    gemm_tf32<<<dim3(2 * Ee / 128, BSr / 128, 1), 256, SMEM>>>(
        mzx, 2 * Ee, wc12, Ee, bc12, z12, 2 * Ee, BSr, 2 * Ee, Ee, 0, 2 * Ee, 1, 0,
        nullptr, nullptr, nullptr, nullptr, nullptr, nullptr, nullptr);

    // 6. dbc (both branches, split-K=8, one launch: grid.z = 16)
    gemm_tf32<<<dim3(1, BSr / 128, 2 * KSPLIT), 256, SMEM>>>(
        z12, 2 * Ee, wdbc1, Ee, nullptr, part, DBCW, BSr, DBCW, Ee, 0, 0,
        KSPLIT, BSr * DBCW,
        z12 + Ee, wdbc2, nullptr, nullptr, nullptr, nullptr, nullptr);

    // 7. reduce both branches -> dbc1, dbc2 (rounded)
    reduce_splitk2<<<(2 * BSr * DBCW + 255) / 256, 256>>>(part, dbc1, dbc2, BSr * DBCW);

    // 8. delta (both branches, one launch: grid.z = 2), softplus epilogue
    gemm_tf32<<<dim3(Ee / 128, BSr / 128, 2), 256, SMEM>>>(
        dbc1, DBCW, wdt1, Rr, bdt1, de1, Ee, BSr, Ee, Rr, 1, 0, 1, 0,
        dbc2, wdt2, bdt2, de2, nullptr, nullptr, nullptr);

    // 9. both selective scans, SMEM-staged
    scan_smem_kernel<<<512, 256>>>(de1, de2, z12, 2 * Ee, dbc1, dbc2,
                                   Alog1, Alog2, Dp1, Dp2, gg1, gg2);

    // 10. acmb = silu(mx) * (gg1 + gg2), rounded
    combine_kernel<<<(BSr * Ee / 4 + 255) / 256, 256>>>(
        (const float4*)mzx, (const float4*)gg1, (const float4*)gg2,
        (float4*)acmb, BSr * Ee / 4);

    // 11. fused final GEMM: out = x + gate * (acmb @ Wf^T + bf + skip)
    gemm_tf32<<<dim3(Dd / 128, BSr / 128, 1), 256, SMEM>>>(
        acmb, Ee, wf, Ee, bf, out, Dd, BSr, Dd, Ee, 3, 0, 1, 0,
        nullptr, nullptr, nullptr, nullptr, x, skip, ada);
}

// round 11
// speedup vs baseline: 1.0060x; 1.0060x over previous
#include <cuda_runtime.h>
#include <cuda_bf16.h>
#include <math.h>
#include <stdint.h>

// Problem constants
#define Bb   2
#define Ss   1024
#define Dd   1024
#define Ee   2048
#define Nn   16
#define Rr   64
#define BSr  (Bb * Ss)          // 2048 rows
#define DBCW (Rr + 2 * Nn)      // 96
#define THREED (3 * Dd)         // 3072
#define KSPLIT 8
#define SCH  64                 // scan chunk (steps per SMEM stage)
#define NCH  (Ss / SCH)         // 16 chunks

// ---------------- scratch (device globals; no allocation in kernel_launch) ----
__device__ float g_ada  [Bb * THREED];
__device__ float g_skip [BSr * Dd];
__device__ float g_xn   [BSr * Dd];
__device__ float g_mzx  [BSr * 2 * Ee];      // mz | mx  (ld = 4096)
__device__ float g_z12  [BSr * 2 * Ee];      // z1 | z2  (ld = 4096)
__device__ float g_dbc1 [BSr * DBCW];
__device__ float g_dbc2 [BSr * DBCW];
__device__ float g_del1 [BSr * Ee];
__device__ float g_del2 [BSr * Ee];
__device__ float g_gg1  [BSr * Ee];
__device__ float g_gg2  [BSr * Ee];
__device__ float g_acmb [BSr * Ee];
__device__ float g_part [2 * KSPLIT * BSr * DBCW];
// pre-rounded (tf32) weights / concat biases
__device__ float g_wzx  [2 * Ee * Dd];       // [Wz ; Wx] rounded
__device__ float g_wc12 [2 * Ee * Ee];       // [Wc1 ; Wc2] rounded
__device__ float g_wdbc1[DBCW * Ee];
__device__ float g_wdbc2[DBCW * Ee];
__device__ float g_wdt1 [Ee * Rr];
__device__ float g_wdt2 [Ee * Rr];
__device__ float g_wf   [Dd * Ee];
__device__ float g_bzx  [2 * Ee];            // [bz ; bx]
__device__ float g_bc12 [2 * Ee];            // [bc1 ; bc2]

// ---------------- helpers -----------------------------------------------------
__device__ __forceinline__ float siluf(float v) { return v / (1.0f + __expf(-v)); }
__device__ __forceinline__ float softplusf(float v) {
    return (v > 20.0f) ? v : log1pf(__expf(v));
}
__device__ __forceinline__ uint32_t f2tf32(float f) {
    uint32_t u;
    asm("cvt.rna.tf32.f32 %0, %1;" : "=r"(u) : "f"(f));
    return u;
}
__device__ __forceinline__ float roundtf(float f) {
    return __uint_as_float(f2tf32(f));
}
__device__ __forceinline__ void mma_tf32(float* c, const uint32_t* a, const uint32_t* b) {
    asm volatile(
        "mma.sync.aligned.m16n8k8.row.col.f32.tf32.tf32.f32 "
        "{%0,%1,%2,%3},{%4,%5,%6,%7},{%8,%9},{%0,%1,%2,%3};"
        : "+f"(c[0]), "+f"(c[1]), "+f"(c[2]), "+f"(c[3])
        : "r"(a[0]), "r"(a[1]), "r"(a[2]), "r"(a[3]), "r"(b[0]), "r"(b[1]));
}
#define CP16(dst, src, sz) \
    asm volatile("cp.async.cg.shared.global [%0], [%1], 16, %2;" \
                 :: "r"(dst), "l"(src), "r"(sz))
#define CP16F(dst, src) \
    asm volatile("cp.async.cg.shared.global [%0], [%1], 16;" \
                 :: "r"(dst), "l"(src))

__device__ __forceinline__ float blockReduceSum(float v, float* sh) {
    int lane = threadIdx.x & 31, wid = threadIdx.x >> 5;
#pragma unroll
    for (int o = 16; o; o >>= 1) v += __shfl_xor_sync(0xffffffffu, v, o);
    __syncthreads();
    if (lane == 0) sh[wid] = v;
    __syncthreads();
    if (wid == 0) {
        v = (lane < 8) ? sh[lane] : 0.0f;
#pragma unroll
        for (int o = 4; o; o >>= 1) v += __shfl_xor_sync(0xffffffffu, v, o);
        if (lane == 0) sh[0] = v;
    }
    __syncthreads();
    return sh[0];
}

// ---------------- fused weight round + bias concat (13 segments) ----------------
#define NSEG 13
struct RoundJobs {
    const float4* src[NSEG];
    float4*       dst[NSEG];
    int           off[NSEG + 1];
    int           rnd[NSEG];
};

__global__ void round_all_kernel(RoundJobs jb, int total4) {
    int i = blockIdx.x * blockDim.x + threadIdx.x;
    if (i >= total4) return;
    int s = 0;
#pragma unroll
    for (int k = 1; k < NSEG; k++) if (i >= jb.off[k]) s = k;
    int j = i - jb.off[s];
    float4 v = jb.src[s][j];
    if (jb.rnd[s]) {
        v.x = roundtf(v.x); v.y = roundtf(v.y);
        v.z = roundtf(v.z); v.w = roundtf(v.w);
    }
    jb.dst[s][j] = v;
}

// ---------------- tf32 tensor-core GEMM (R9 mainloop, 3-stage cp.async) ---------
// C[M,N] = A[M,K] * W[N,K]^T (+bias, +epi). Tile 128x128x32, 256 threads,
// 8 warps (2x4), warp tile 64x32, mma m16n8k8 tf32. 3-stage cp.async pipeline,
// issue-before-wait ordering (measured fastest), XOR-swizzled SMEM.
// epi: 0 none, 1 softplus, 3 fused ViM final (out = x + gate*(acc+bias+skip)).
// nRound: columns [0,nRound) rna-rounded on store.
// Batching: blockIdx.z in [0, splitK * nBranch); branch = z / splitK selects
// (A2,W2,bias2,C2). Output at C + z*partStride (bias only when splitK == 1).
__global__ __launch_bounds__(256, 2) void gemm_tf32(
    const float* __restrict__ A_, int lda,
    const float* __restrict__ W_, int ldb,
    const float* __restrict__ bias_,
    float* __restrict__ C_, int ldc,
    int M, int N, int K, int epi, int nRound, int splitK, int partStride,
    const float* A2, const float* W2, const float* bias2, float* C2,
    const float* xP, const float* skipP, const float* adaP)
{
    extern __shared__ float smf[];
    float* As = smf;             // [3][128*32]
    float* Bs = smf + 12288;     // [3][128*32]

    const float* A = A_;
    const float* W = W_;
    const float* bias = bias_;
    float* C = C_;

    const int bz = blockIdx.z;
    const int br = bz / splitK;
    const int kz = bz % splitK;
    if (br == 1) { A = A2; W = W2; bias = bias2; if (C2) C = C2; }

    const int tid  = threadIdx.x;
    const int wid  = tid >> 5, lane = tid & 31;
    const int wm   = wid >> 2, wn = wid & 3;
    const int grp  = lane >> 2, tig = lane & 3;
    const int bm   = blockIdx.y * 128, bn = blockIdx.x * 128;
    const int klen   = K / splitK;
    const int kstart = kz * klen;
    const int ntile  = klen >> 5;

    float acc[4][4][4];
#pragma unroll
    for (int i = 0; i < 4; i++)
#pragma unroll
        for (int j = 0; j < 4; j++)
#pragma unroll
            for (int r = 0; r < 4; r++) acc[i][j][r] = 0.0f;

    uint32_t aSm[4], bSm[4], bSz[4];
    const float* aP[4];
    const float* bP[4];
    const uint32_t sA = (uint32_t)__cvta_generic_to_shared(As);
    const uint32_t sB = (uint32_t)__cvta_generic_to_shared(Bs);
#pragma unroll
    for (int i = 0; i < 4; i++) {
        int f = tid + i * 256;
        int m = f >> 3, kq = (f & 7) * 4;
        int col = kq ^ ((m & 7) << 2);
        aSm[i] = sA + (uint32_t)(m * 32 + col) * 4u;
        bSm[i] = sB + (uint32_t)(m * 32 + col) * 4u;
        aP[i]  = A + (size_t)(bm + m) * lda + kstart + kq;
        int brow = bn + m;
        bSz[i] = (brow < N) ? 16u : 0u;
        if (brow >= N) brow = N - 1;
        bP[i]  = W + (size_t)brow * ldb + kstart + kq;
    }

    // prologue: stages 0 and 1
#pragma unroll
    for (int st = 0; st < 2; st++) {
        if (st < ntile) {
            const uint32_t so = (uint32_t)st * 16384u;
#pragma unroll
            for (int i = 0; i < 4; i++) {
                CP16(aSm[i] + so, aP[i], 16u);
                CP16(bSm[i] + so, bP[i], bSz[i]);
                aP[i] += 32; bP[i] += 32;
            }
            asm volatile("cp.async.commit_group;");
        }
    }

    const int swz = grp << 2;

    for (int t = 0; t < ntile; t++) {
        if (t + 2 < ntile) {
            const int st = (t + 2) % 3;
            const uint32_t so = (uint32_t)st * 16384u;
#pragma unroll
            for (int i = 0; i < 4; i++) {
                CP16(aSm[i] + so, aP[i], 16u);
                CP16(bSm[i] + so, bP[i], bSz[i]);
                aP[i] += 32; bP[i] += 32;
            }
            asm volatile("cp.async.commit_group;");
            asm volatile("cp.async.wait_group 2;");
        } else if (t + 1 < ntile) {
            asm volatile("cp.async.wait_group 1;");
        } else {
            asm volatile("cp.async.wait_group 0;");
        }
        __syncthreads();

        const int buf = (t % 3) * 4096;
#pragma unroll
        for (int ks = 0; ks < 4; ks++) {
            const int kb = ks * 8;
            const int c0 = (kb + tig) ^ swz;
            const int c1 = (kb + tig + 4) ^ swz;
            uint32_t af[4][4], bf[4][2];
#pragma unroll
            for (int mt = 0; mt < 4; mt++) {
                int r0 = (wm * 64 + mt * 16 + grp) * 32;
                af[mt][0] = __float_as_uint(As[buf + r0 + c0]);
                af[mt][1] = __float_as_uint(As[buf + r0 + 256 + c0]);
                af[mt][2] = __float_as_uint(As[buf + r0 + c1]);
                af[mt][3] = __float_as_uint(As[buf + r0 + 256 + c1]);
            }
#pragma unroll
            for (int nt = 0; nt < 4; nt++) {
                int r0 = (wn * 32 + nt * 8 + grp) * 32;
                bf[nt][0] = __float_as_uint(Bs[buf + r0 + c0]);
                bf[nt][1] = __float_as_uint(Bs[buf + r0 + c1]);
            }
#pragma unroll
            for (int mt = 0; mt < 4; mt++)
#pragma unroll
                for (int nt = 0; nt < 4; nt++)
                    mma_tf32(acc[mt][nt], af[mt], bf[nt]);
        }
        __syncthreads();
    }

    float* Cp = C + (size_t)bz * partStride;
    const bool doBias = (bias != nullptr) && (splitK == 1);
#pragma unroll
    for (int mt = 0; mt < 4; mt++) {
#pragma unroll
        for (int nt = 0; nt < 4; nt++) {
            int row = bm + wm * 64 + mt * 16 + grp;
            int col = bn + wn * 32 + nt * 8 + tig * 2;
            if (col >= N) continue;
            float b0 = doBias ? __ldg(bias + col) : 0.0f;
            float b1 = doBias ? __ldg(bias + col + 1) : 0.0f;
            float v0 = acc[mt][nt][0] + b0, v1 = acc[mt][nt][1] + b1;
            float v2 = acc[mt][nt][2] + b0, v3 = acc[mt][nt][3] + b1;
            if (epi == 1) {
                v0 = softplusf(v0); v1 = softplusf(v1);
                v2 = softplusf(v2); v3 = softplusf(v3);
            } else if (epi == 3) {
                // out = x + gate * (acc + bias + skip)
                int bb = row >> 10;
                float g0 = __ldg(adaP + bb * THREED + 2 * Dd + col);
                float g1 = __ldg(adaP + bb * THREED + 2 * Dd + col + 1);
                size_t i0 = (size_t)row * Dd + col;
                size_t i1 = (size_t)(row + 8) * Dd + col;
                v0 = __ldg(xP + i0)     + g0 * (v0 + __ldg(skipP + i0));
                v1 = __ldg(xP + i0 + 1) + g1 * (v1 + __ldg(skipP + i0 + 1));
                v2 = __ldg(xP + i1)     + g0 * (v2 + __ldg(skipP + i1));
                v3 = __ldg(xP + i1 + 1) + g1 * (v3 + __ldg(skipP + i1 + 1));
            }
            if (col < nRound) {
                v0 = roundtf(v0); v1 = roundtf(v1);
                v2 = roundtf(v2); v3 = roundtf(v3);
            }
            float2 lo = make_float2(v0, v1), hi = make_float2(v2, v3);
            *(float2*)&Cp[(size_t)row * ldc + col] = lo;
            *(float2*)&Cp[(size_t)(row + 8) * ldc + col] = hi;
        }
    }
}

// ---------------- split-K reduction for both branches (rounds output) ------------
__global__ void reduce_splitk2(const float* __restrict__ part,
                               float* __restrict__ out1,
                               float* __restrict__ out2, int n)
{
    int i = blockIdx.x * blockDim.x + threadIdx.x;
    if (i < 2 * n) {
        int br = (i >= n);
        int j  = i - br * n;
        const float* p = part + (size_t)(br * KSPLIT) * n + j;
        float s = 0.0f;
#pragma unroll
        for (int z = 0; z < KSPLIT; z++) s += p[(size_t)z * n];
        float v = roundtf(s);
        if (br) out2[j] = v; else out1[j] = v;
    }
}

// ---------------- ada: one warp computes both batch outputs ----------------------
__global__ __launch_bounds__(256) void ada_kernel(
    const float* __restrict__ c, const float* __restrict__ Wada,
    const float* __restrict__ bada, float* __restrict__ ada)
{
    int w    = (blockIdx.x * blockDim.x + threadIdx.x) >> 5;   // 0..3071
    int lane = threadIdx.x & 31;

    const float4* wp  = (const float4*)(Wada + (size_t)w * 2 * Dd);
    const float4* c0p = (const float4*)c;
    const float4* c1p = (const float4*)(c + 2 * Dd);
    float s0 = 0.0f, s1 = 0.0f;
#pragma unroll
    for (int it = 0; it < 16; it++) {
        float4 wv = __ldg(&wp[lane + it * 32]);
        float4 a0 = __ldg(&c0p[lane + it * 32]);
        float4 a1 = __ldg(&c1p[lane + it * 32]);
        s0 += siluf(a0.x) * wv.x + siluf(a0.y) * wv.y
            + siluf(a0.z) * wv.z + siluf(a0.w) * wv.w;
        s1 += siluf(a1.x) * wv.x + siluf(a1.y) * wv.y
            + siluf(a1.z) * wv.z + siluf(a1.w) * wv.w;
    }
#pragma unroll
    for (int off = 16; off; off >>= 1) {
        s0 += __shfl_xor_sync(0xffffffffu, s0, off);
        s1 += __shfl_xor_sync(0xffffffffu, s1, off);
    }
    if (lane == 0) {
        float bv = __ldg(bada + w);
        ada[w] = s0 + bv;
        ada[THREED + w] = s1 + bv;
    }
}

// ---------------- fused LN1 + modulate(+store skip) + LN2 (xn rounded) -----------
__global__ __launch_bounds__(256) void ln_mod_kernel(
    const float* __restrict__ x,
    const float* __restrict__ g1, const float* __restrict__ b1,
    const float* __restrict__ g2, const float* __restrict__ b2,
    const float* __restrict__ ada,
    float* __restrict__ skip, float* __restrict__ xn)
{
    __shared__ float sh[8];
    const int row = blockIdx.x;
    const int b = row >> 10;
    const float* xr = x + (size_t)row * Dd;

    float v[4];
#pragma unroll
    for (int j = 0; j < 4; j++) v[j] = xr[threadIdx.x + j * 256];

    float s1 = 0.0f, s2 = 0.0f;
#pragma unroll
    for (int j = 0; j < 4; j++) { s1 += v[j]; s2 += v[j] * v[j]; }
    s1 = blockReduceSum(s1, sh);
    s2 = blockReduceSum(s2, sh);
    float m  = s1 * (1.0f / Dd);
    float rs = rsqrtf(s2 * (1.0f / Dd) - m * m + 1e-5f);

    float t[4];
    s1 = 0.0f; s2 = 0.0f;
#pragma unroll
    for (int j = 0; j < 4; j++) {
        int d = threadIdx.x + j * 256;
        float tt = (v[j] - m) * rs * g1[d] + b1[d];
        tt = tt * (1.0f + ada[b * THREED + Dd + d]) + ada[b * THREED + d];
        t[j] = tt;
        skip[(size_t)row * Dd + d] = tt;
        s1 += tt; s2 += tt * tt;
    }
    s1 = blockReduceSum(s1, sh);
    s2 = blockReduceSum(s2, sh);
    float m2  = s1 * (1.0f / Dd);
    float rs2 = rsqrtf(s2 * (1.0f / Dd) - m2 * m2 + 1e-5f);

#pragma unroll
    for (int j = 0; j < 4; j++) {
        int d = threadIdx.x + j * 256;
        xn[(size_t)row * Dd + d] = roundtf((t[j] - m2) * rs2 * g2[d] + b2[d]);
    }
}

// ---------------- SMEM-staged selective scan -------------------------------------
__global__ __launch_bounds__(256) void scan_smem_kernel(
    const float* __restrict__ de1, const float* __restrict__ de2,
    const float* __restrict__ z12, int ldz,
    const float* __restrict__ dbc1, const float* __restrict__ dbc2,
    const float* __restrict__ Alog1, const float* __restrict__ Alog2,
    const float* __restrict__ Dp1, const float* __restrict__ Dp2,
    float* __restrict__ gg1, float* __restrict__ gg2)
{
    __shared__ float deS[2][SCH][16];
    __shared__ float zS [2][SCH][16];
    __shared__ float bcS[2][SCH][32];
    __shared__ float ggS[SCH][16];

    const int tid = threadIdx.x;
    const int u   = tid >> 4;
    const int n   = tid & 15;

    const int bx = blockIdx.x;         // 0..511
    const int et = bx & 127;
    const int b  = (bx >> 7) & 1;
    const int br = bx >> 8;
    const int e0 = et * 16;

    const float* de   = br ? de2  : de1;
    const float* z    = z12 + (br ? Ee : 0);
    const float* dbc  = br ? dbc2 : dbc1;
    const float* Alog = br ? Alog2 : Alog1;
    const float* Dp   = br ? Dp2  : Dp1;
    float*       gg   = br ? gg2  : gg1;

    const int e = e0 + u;
    const float A_n  = -__expf(Alog[e * Nn + n]);
    const float Dp_e = Dp[e];

    const size_t rowBase = (size_t)b * Ss;

    uint32_t deSm = (uint32_t)__cvta_generic_to_shared(&deS[0][0][0]);
    uint32_t zSm  = (uint32_t)__cvta_generic_to_shared(&zS[0][0][0]);
    uint32_t bcSm = (uint32_t)__cvta_generic_to_shared(&bcS[0][0][0]);

    const int lr  = tid >> 2;
    const int lp  = (tid & 3) * 4;
    const int br0 = (tid * 2) >> 3;
    const int bp0 = ((tid * 2) & 7) * 4;
    const int br1 = (tid * 2 + 1) >> 3;
    const int bp1 = ((tid * 2 + 1) & 7) * 4;

    auto loadChunk = [&](int c, int buf) {
        int s = br ? (Ss - 1 - (c * SCH + lr)) : (c * SCH + lr);
        const float* gd = de + (rowBase + s) * Ee + e0 + lp;
        const float* gz = z  + (rowBase + s) * (size_t)ldz + e0 + lp;
        CP16F(deSm + (uint32_t)((buf * SCH + lr) * 16 + lp) * 4u, gd);
        CP16F(zSm  + (uint32_t)((buf * SCH + lr) * 16 + lp) * 4u, gz);
        int s0 = br ? (Ss - 1 - (c * SCH + br0)) : (c * SCH + br0);
        int s1b = br ? (Ss - 1 - (c * SCH + br1)) : (c * SCH + br1);
        const float* g0 = dbc + (rowBase + s0) * DBCW + Rr + bp0;
        const float* g1 = dbc + (rowBase + s1b) * DBCW + Rr + bp1;
        CP16F(bcSm + (uint32_t)((buf * SCH + br0) * 32 + bp0) * 4u, g0);
        CP16F(bcSm + (uint32_t)((buf * SCH + br1) * 32 + bp1) * 4u, g1);
    };

    loadChunk(0, 0);
    asm volatile("cp.async.commit_group;");

    float h = 0.0f;

    for (int c = 0; c < NCH; c++) {
        if (c + 1 < NCH) {
            loadChunk(c + 1, (c + 1) & 1);
            asm volatile("cp.async.commit_group;");
            asm volatile("cp.async.wait_group 1;");
        } else {
            asm volatile("cp.async.wait_group 0;");
        }
        __syncthreads();

        const int buf = c & 1;
#pragma unroll 8
        for (int cs = 0; cs < SCH; cs++) {
            float dlt = deS[buf][cs][u];
            float uu  = zS[buf][cs][u];
            float Bv  = bcS[buf][cs][n];
            float Cv  = bcS[buf][cs][16 + n];

            h = __expf(dlt * A_n) * h + dlt * Bv * uu;
            float y = h * Cv;
            y += __shfl_xor_sync(0xffffffffu, y, 8);
            y += __shfl_xor_sync(0xffffffffu, y, 4);
            y += __shfl_xor_sync(0xffffffffu, y, 2);
            y += __shfl_xor_sync(0xffffffffu, y, 1);
            if (n == 0) ggS[cs][u] = y + uu * Dp_e;
        }
        __syncthreads();

        {
            int r = tid >> 2, p = (tid & 3) * 4;
            int s = br ? (Ss - 1 - (c * SCH + r)) : (c * SCH + r);
            *(float4*)&gg[(rowBase + s) * Ee + e0 + p] = *(float4*)&ggS[r][p];
        }
    }
}

// ---------------- acmb = silu(mx) * (gg1 + gg2), rounded --------------------------
__global__ void combine_kernel(const float4* __restrict__ mzx,
                               const float4* __restrict__ gg1,
                               const float4* __restrict__ gg2,
                               float4* __restrict__ a, int n4)
{
    int i = blockIdx.x * blockDim.x + threadIdx.x;
    if (i < n4) {
        int row  = i >> 9;              // / (Ee/4)
        int col4 = i & 511;
        float4 m = mzx[row * 1024 + 512 + col4];   // mx half (ld=4096 floats)
        float4 p = gg1[i], q = gg2[i], r;
        r.x = roundtf(siluf(m.x) * (p.x + q.x));
        r.y = roundtf(siluf(m.y) * (p.y + q.y));
        r.z = roundtf(siluf(m.z) * (p.z + q.z));
        r.w = roundtf(siluf(m.w) * (p.w + q.w));
        a[i] = r;
    }
}

// ---------------- host launcher ----------------------------------------------------
extern "C" void kernel_launch(void* const* d_in, const int* in_sizes, int n_in,
                              void* d_out, int out_size)
{
    const float* x     = (const float*)d_in[0];
    const float* c     = (const float*)d_in[1];
    const float* n1g   = (const float*)d_in[3];
    const float* n1b   = (const float*)d_in[4];
    const float* n2g   = (const float*)d_in[5];
    const float* n2b   = (const float*)d_in[6];
    const float* Wx    = (const float*)d_in[7];
    const float* bx    = (const float*)d_in[8];
    const float* Wz    = (const float*)d_in[9];
    const float* bz    = (const float*)d_in[10];
    const float* Wf    = (const float*)d_in[11];
    const float* bf    = (const float*)d_in[12];
    const float* Wada  = (const float*)d_in[13];
    const float* bada  = (const float*)d_in[14];
    const float* Wc1   = (const float*)d_in[15];
    const float* bc1   = (const float*)d_in[16];
    const float* Wc2   = (const float*)d_in[17];
    const float* bc2   = (const float*)d_in[18];
    const float* Wdbc1 = (const float*)d_in[19];
    const float* Wdt1  = (const float*)d_in[20];
    const float* bdt1  = (const float*)d_in[21];
    const float* Alog1 = (const float*)d_in[22];
    const float* Dp1   = (const float*)d_in[23];
    const float* Wdbc2 = (const float*)d_in[24];
    const float* Wdt2  = (const float*)d_in[25];
    const float* bdt2  = (const float*)d_in[26];
    const float* Alog2 = (const float*)d_in[27];
    const float* Dp2   = (const float*)d_in[28];
    float* out = (float*)d_out;

    float *ada, *skip, *xn, *mzx, *z12, *dbc1, *dbc2;
    float *de1, *de2, *gg1, *gg2, *acmb, *part;
    float *wzx, *wc12, *wdbc1, *wdbc2, *wdt1, *wdt2, *wf, *bzx, *bc12;
    cudaGetSymbolAddress((void**)&ada,  g_ada);
    cudaGetSymbolAddress((void**)&skip, g_skip);
    cudaGetSymbolAddress((void**)&xn,   g_xn);
    cudaGetSymbolAddress((void**)&mzx,  g_mzx);
    cudaGetSymbolAddress((void**)&z12,  g_z12);
    cudaGetSymbolAddress((void**)&dbc1, g_dbc1);
    cudaGetSymbolAddress((void**)&dbc2, g_dbc2);
    cudaGetSymbolAddress((void**)&de1,  g_del1);
    cudaGetSymbolAddress((void**)&de2,  g_del2);
    cudaGetSymbolAddress((void**)&gg1,  g_gg1);
    cudaGetSymbolAddress((void**)&gg2,  g_gg2);
    cudaGetSymbolAddress((void**)&acmb, g_acmb);
    cudaGetSymbolAddress((void**)&part, g_part);
    cudaGetSymbolAddress((void**)&wzx,   g_wzx);
    cudaGetSymbolAddress((void**)&wc12,  g_wc12);
    cudaGetSymbolAddress((void**)&wdbc1, g_wdbc1);
    cudaGetSymbolAddress((void**)&wdbc2, g_wdbc2);
    cudaGetSymbolAddress((void**)&wdt1,  g_wdt1);
    cudaGetSymbolAddress((void**)&wdt2,  g_wdt2);
    cudaGetSymbolAddress((void**)&wf,    g_wf);
    cudaGetSymbolAddress((void**)&bzx,   g_bzx);
    cudaGetSymbolAddress((void**)&bc12,  g_bc12);

    const int SMEM = 98304;   // 3-stage pipeline: 2 x 3 x 16KB
    cudaFuncSetAttribute(gemm_tf32, cudaFuncAttributeMaxDynamicSharedMemorySize, SMEM);

    // 1. fused weight round + bias concat (one launch)
    {
        RoundJobs jb;
        const float* srcs[NSEG] = { Wz, Wx, Wc1, Wc2, Wdbc1, Wdbc2, Wdt1, Wdt2, Wf,
                                    bz, bx, bc1, bc2 };
        float* dsts[NSEG] = { wzx, wzx + (size_t)Ee * Dd,
                              wc12, wc12 + (size_t)Ee * Ee,
                              wdbc1, wdbc2, wdt1, wdt2, wf,
                              bzx, bzx + Ee, bc12, bc12 + Ee };
        int sizes4[NSEG] = { Ee * Dd / 4, Ee * Dd / 4, Ee * Ee / 4, Ee * Ee / 4,
                             DBCW * Ee / 4, DBCW * Ee / 4, Ee * Rr / 4, Ee * Rr / 4,
                             Dd * Ee / 4, Ee / 4, Ee / 4, Ee / 4, Ee / 4 };
        int rnds[NSEG] = { 1,1,1,1,1,1,1,1,1, 0,0,0,0 };
        int off = 0;
        for (int s = 0; s < NSEG; s++) {
            jb.src[s] = (const float4*)srcs[s];
            jb.dst[s] = (float4*)dsts[s];
            jb.off[s] = off;
            jb.rnd[s] = rnds[s];
            off += sizes4[s];
        }
        jb.off[NSEG] = off;
        round_all_kernel<<<(off + 255) / 256, 256>>>(jb, off);
    }

    // 2. ada = silu(c) @ Wada^T + bada  (one warp -> both batch rows)
    ada_kernel<<<384, 256>>>(c, Wada, bada, ada);

    // 3. LN1 + modulate (-> skip) + LN2 (-> xn, rounded)
    ln_mod_kernel<<<BSr, 256>>>(x, n1g, n1b, n2g, n2b, ada, skip, xn);

    // 4. merged mz|mx  [2048, 4096] K=1024
    gemm_tf32<<<dim3(2 * Ee / 128, BSr / 128, 1), 256, SMEM>>>(
        xn, Dd, wzx, Dd, bzx, mzx, 2 * Ee, BSr, 2 * Ee, Dd, 0, Ee, 1, 0,
        nullptr, nullptr, nullptr, nullptr, nullptr, nullptr, nullptr);

    // 5. merged z1|z2  [2048, 4096] K=2048 (A = mz half of mzx, lda=4096)
    gemm_tf32<<<dim3(2 * Ee / 128, BSr / 128, 1), 256, SMEM>>>(
        mzx, 2 * Ee, wc12, Ee, bc12, z12, 2 * Ee, BSr, 2 * Ee, Ee, 0, 2 * Ee, 1, 0,
        nullptr, nullptr, nullptr, nullptr, nullptr, nullptr, nullptr);

    // 6. dbc (both branches, split-K=8, one launch: grid.z = 16)
    gemm_tf32<<<dim3(1, BSr / 128, 2 * KSPLIT), 256, SMEM>>>(
        z12, 2 * Ee, wdbc1, Ee, nullptr, part, DBCW, BSr, DBCW, Ee, 0, 0,
        KSPLIT, BSr * DBCW,
        z12 + Ee, wdbc2, nullptr, nullptr, nullptr, nullptr, nullptr);

    // 7. reduce both branches -> dbc1, dbc2 (rounded)
    reduce_splitk2<<<(2 * BSr * DBCW + 255) / 256, 256>>>(part, dbc1, dbc2, BSr * DBCW);

    // 8. delta (both branches, one launch: grid.z = 2), softplus epilogue
    gemm_tf32<<<dim3(Ee / 128, BSr / 128, 2), 256, SMEM>>>(
        dbc1, DBCW, wdt1, Rr, bdt1, de1, Ee, BSr, Ee, Rr, 1, 0, 1, 0,
        dbc2, wdt2, bdt2, de2, nullptr, nullptr, nullptr);

    // 9. both selective scans, SMEM-staged
    scan_smem_kernel<<<512, 256>>>(de1, de2, z12, 2 * Ee, dbc1, dbc2,
                                   Alog1, Alog2, Dp1, Dp2, gg1, gg2);

    // 10. acmb = silu(mx) * (gg1 + gg2), rounded
    combine_kernel<<<(BSr * Ee / 4 + 255) / 256, 256>>>(
        (const float4*)mzx, (const float4*)gg1, (const float4*)gg2,
        (float4*)acmb, BSr * Ee / 4);

    // 11. fused final GEMM: out = x + gate * (acmb @ Wf^T + bf + skip)
    gemm_tf32<<<dim3(Dd / 128, BSr / 128, 1), 256, SMEM>>>(
        acmb, Ee, wf, Ee, bf, out, Dd, BSr, Dd, Ee, 3, 0, 1, 0,
        nullptr, nullptr, nullptr, nullptr, x, skip, ada);
}

// round 12
// speedup vs baseline: 1.0363x; 1.0301x over previous
#include <cuda_runtime.h>
#include <cuda_bf16.h>
#include <math.h>
#include <stdint.h>

// Problem constants
#define Bb   2
#define Ss   1024
#define Dd   1024
#define Ee   2048
#define Nn   16
#define Rr   64
#define BSr  (Bb * Ss)          // 2048 rows
#define DBCW (Rr + 2 * Nn)      // 96
#define THREED (3 * Dd)         // 3072
#define KSPLIT 8
#define SCH  64                 // scan chunk (steps per SMEM stage)
#define NCH  (Ss / SCH)         // 16 chunks

// ---------------- scratch (device globals; no allocation in kernel_launch) ----
__device__ float g_ada  [Bb * THREED];
__device__ float g_skip [BSr * Dd];
__device__ float g_xn   [BSr * Dd];
__device__ float g_mzx  [BSr * 2 * Ee];      // mz | mx  (ld = 4096)
__device__ float g_z12  [BSr * 2 * Ee];      // z1 | z2  (ld = 4096)
__device__ float g_dbc1 [BSr * DBCW];
__device__ float g_dbc2 [BSr * DBCW];
__device__ float g_del1 [BSr * Ee];
__device__ float g_del2 [BSr * Ee];
__device__ float g_gg1  [BSr * Ee];
__device__ float g_gg2  [BSr * Ee];
__device__ float g_acmb [BSr * Ee];
__device__ float g_part [2 * KSPLIT * BSr * DBCW];
// pre-rounded (tf32) weights / concat biases
__device__ float g_wzx  [2 * Ee * Dd];       // [Wz ; Wx] rounded
__device__ float g_wc12 [2 * Ee * Ee];       // [Wc1 ; Wc2] rounded
__device__ float g_wdbc1[DBCW * Ee];
__device__ float g_wdbc2[DBCW * Ee];
__device__ float g_wdt1 [Ee * Rr];
__device__ float g_wdt2 [Ee * Rr];
__device__ float g_wf   [Dd * Ee];
__device__ float g_bzx  [2 * Ee];            // [bz ; bx]
__device__ float g_bc12 [2 * Ee];            // [bc1 ; bc2]

// ---------------- helpers -----------------------------------------------------
__device__ __forceinline__ float siluf(float v) { return v / (1.0f + __expf(-v)); }
__device__ __forceinline__ float softplusf(float v) {
    return (v > 20.0f) ? v : log1pf(__expf(v));
}
__device__ __forceinline__ uint32_t f2tf32(float f) {
    uint32_t u;
    asm("cvt.rna.tf32.f32 %0, %1;" : "=r"(u) : "f"(f));
    return u;
}
__device__ __forceinline__ float roundtf(float f) {
    return __uint_as_float(f2tf32(f));
}
__device__ __forceinline__ void mma_tf32(float* c, const uint32_t* a, const uint32_t* b) {
    asm volatile(
        "mma.sync.aligned.m16n8k8.row.col.f32.tf32.tf32.f32 "
        "{%0,%1,%2,%3},{%4,%5,%6,%7},{%8,%9},{%0,%1,%2,%3};"
        : "+f"(c[0]), "+f"(c[1]), "+f"(c[2]), "+f"(c[3])
        : "r"(a[0]), "r"(a[1]), "r"(a[2]), "r"(a[3]), "r"(b[0]), "r"(b[1]));
}
#define CP16(dst, src, sz) \
    asm volatile("cp.async.cg.shared.global [%0], [%1], 16, %2;" \
                 :: "r"(dst), "l"(src), "r"(sz))
#define CP16F(dst, src) \
    asm volatile("cp.async.cg.shared.global [%0], [%1], 16;" \
                 :: "r"(dst), "l"(src))

__device__ __forceinline__ float blockReduceSum(float v, float* sh) {
    int lane = threadIdx.x & 31, wid = threadIdx.x >> 5;
#pragma unroll
    for (int o = 16; o; o >>= 1) v += __shfl_xor_sync(0xffffffffu, v, o);
    __syncthreads();
    if (lane == 0) sh[wid] = v;
    __syncthreads();
    if (wid == 0) {
        v = (lane < 8) ? sh[lane] : 0.0f;
#pragma unroll
        for (int o = 4; o; o >>= 1) v += __shfl_xor_sync(0xffffffffu, v, o);
        if (lane == 0) sh[0] = v;
    }
    __syncthreads();
    return sh[0];
}

// ---------------- fused weight round + bias concat (13 segments) ----------------
#define NSEG 13
struct RoundJobs {
    const float4* src[NSEG];
    float4*       dst[NSEG];
    int           off[NSEG + 1];
    int           rnd[NSEG];
};

__global__ void round_all_kernel(RoundJobs jb, int total4) {
    int i = blockIdx.x * blockDim.x + threadIdx.x;
    if (i >= total4) return;
    int s = 0;
#pragma unroll
    for (int k = 1; k < NSEG; k++) if (i >= jb.off[k]) s = k;
    int j = i - jb.off[s];
    float4 v = jb.src[s][j];
    if (jb.rnd[s]) {
        v.x = roundtf(v.x); v.y = roundtf(v.y);
        v.z = roundtf(v.z); v.w = roundtf(v.w);
    }
    jb.dst[s][j] = v;
}

// ---------------- tf32 tensor-core GEMM (templated epilogue) --------------------
// C[M,N] = A[M,K] * W[N,K]^T (+bias, +epi). Tile 128x128x32, 256 threads,
// 8 warps (2x4), warp tile 64x32, mma m16n8k8 tf32. 3-stage cp.async pipeline,
// issue-before-wait ordering (measured fastest), XOR-swizzled SMEM.
// EPI (compile-time): 0 none, 1 softplus, 3 fused ViM final
// (out = x + gate*(acc+bias+skip)). Each instantiation carries ONLY its own
// epilogue code so hot-path codegen is unpolluted.
// nRound: columns [0,nRound) rna-rounded on store.
// Batching: blockIdx.z in [0, splitK * nBranch); branch = z / splitK selects
// (A2,W2,bias2,C2). Output at C + z*partStride (bias only when splitK == 1).
template <int EPI>
__global__ __launch_bounds__(256, 2) void gemm_tf32(
    const float* __restrict__ A_, int lda,
    const float* __restrict__ W_, int ldb,
    const float* __restrict__ bias_,
    float* __restrict__ C_, int ldc,
    int M, int N, int K, int nRound, int splitK, int partStride,
    const float* A2, const float* W2, const float* bias2, float* C2,
    const float* xP, const float* skipP, const float* adaP)
{
    extern __shared__ float smf[];
    float* As = smf;             // [3][128*32]
    float* Bs = smf + 12288;     // [3][128*32]

    const float* A = A_;
    const float* W = W_;
    const float* bias = bias_;
    float* C = C_;

    const int bz = blockIdx.z;
    const int br = bz / splitK;
    const int kz = bz % splitK;
    if (br == 1) { A = A2; W = W2; bias = bias2; if (C2) C = C2; }

    const int tid  = threadIdx.x;
    const int wid  = tid >> 5, lane = tid & 31;
    const int wm   = wid >> 2, wn = wid & 3;
    const int grp  = lane >> 2, tig = lane & 3;
    const int bm   = blockIdx.y * 128, bn = blockIdx.x * 128;
    const int klen   = K / splitK;
    const int kstart = kz * klen;
    const int ntile  = klen >> 5;

    float acc[4][4][4];
#pragma unroll
    for (int i = 0; i < 4; i++)
#pragma unroll
        for (int j = 0; j < 4; j++)
#pragma unroll
            for (int r = 0; r < 4; r++) acc[i][j][r] = 0.0f;

    uint32_t aSm[4], bSm[4], bSz[4];
    const float* aP[4];
    const float* bP[4];
    const uint32_t sA = (uint32_t)__cvta_generic_to_shared(As);
    const uint32_t sB = (uint32_t)__cvta_generic_to_shared(Bs);
#pragma unroll
    for (int i = 0; i < 4; i++) {
        int f = tid + i * 256;
        int m = f >> 3, kq = (f & 7) * 4;
        int col = kq ^ ((m & 7) << 2);
        aSm[i] = sA + (uint32_t)(m * 32 + col) * 4u;
        bSm[i] = sB + (uint32_t)(m * 32 + col) * 4u;
        aP[i]  = A + (size_t)(bm + m) * lda + kstart + kq;
        int brow = bn + m;
        bSz[i] = (brow < N) ? 16u : 0u;
        if (brow >= N) brow = N - 1;
        bP[i]  = W + (size_t)brow * ldb + kstart + kq;
    }

    // prologue: stages 0 and 1
#pragma unroll
    for (int st = 0; st < 2; st++) {
        if (st < ntile) {
            const uint32_t so = (uint32_t)st * 16384u;
#pragma unroll
            for (int i = 0; i < 4; i++) {
                CP16(aSm[i] + so, aP[i], 16u);
                CP16(bSm[i] + so, bP[i], bSz[i]);
                aP[i] += 32; bP[i] += 32;
            }
            asm volatile("cp.async.commit_group;");
        }
    }

    const int swz = grp << 2;

    for (int t = 0; t < ntile; t++) {
        if (t + 2 < ntile) {
            const int st = (t + 2) % 3;
            const uint32_t so = (uint32_t)st * 16384u;
#pragma unroll
            for (int i = 0; i < 4; i++) {
                CP16(aSm[i] + so, aP[i], 16u);
                CP16(bSm[i] + so, bP[i], bSz[i]);
                aP[i] += 32; bP[i] += 32;
            }
            asm volatile("cp.async.commit_group;");
            asm volatile("cp.async.wait_group 2;");
        } else if (t + 1 < ntile) {
            asm volatile("cp.async.wait_group 1;");
        } else {
            asm volatile("cp.async.wait_group 0;");
        }
        __syncthreads();

        const int buf = (t % 3) * 4096;
#pragma unroll
        for (int ks = 0; ks < 4; ks++) {
            const int kb = ks * 8;
            const int c0 = (kb + tig) ^ swz;
            const int c1 = (kb + tig + 4) ^ swz;
            uint32_t af[4][4], bf[4][2];
#pragma unroll
            for (int mt = 0; mt < 4; mt++) {
                int r0 = (wm * 64 + mt * 16 + grp) * 32;
                af[mt][0] = __float_as_uint(As[buf + r0 + c0]);
                af[mt][1] = __float_as_uint(As[buf + r0 + 256 + c0]);
                af[mt][2] = __float_as_uint(As[buf + r0 + c1]);
                af[mt][3] = __float_as_uint(As[buf + r0 + 256 + c1]);
            }
#pragma unroll
            for (int nt = 0; nt < 4; nt++) {
                int r0 = (wn * 32 + nt * 8 + grp) * 32;
                bf[nt][0] = __float_as_uint(Bs[buf + r0 + c0]);
                bf[nt][1] = __float_as_uint(Bs[buf + r0 + c1]);
            }
#pragma unroll
            for (int mt = 0; mt < 4; mt++)
#pragma unroll
                for (int nt = 0; nt < 4; nt++)
                    mma_tf32(acc[mt][nt], af[mt], bf[nt]);
        }
        __syncthreads();
    }

    float* Cp = C + (size_t)bz * partStride;
    const bool doBias = (bias != nullptr) && (splitK == 1);
#pragma unroll
    for (int mt = 0; mt < 4; mt++) {
#pragma unroll
        for (int nt = 0; nt < 4; nt++) {
            int row = bm + wm * 64 + mt * 16 + grp;
            int col = bn + wn * 32 + nt * 8 + tig * 2;
            if (col >= N) continue;
            float b0 = doBias ? __ldg(bias + col) : 0.0f;
            float b1 = doBias ? __ldg(bias + col + 1) : 0.0f;
            float v0 = acc[mt][nt][0] + b0, v1 = acc[mt][nt][1] + b1;
            float v2 = acc[mt][nt][2] + b0, v3 = acc[mt][nt][3] + b1;
            if (EPI == 1) {
                v0 = softplusf(v0); v1 = softplusf(v1);
                v2 = softplusf(v2); v3 = softplusf(v3);
            } else if (EPI == 3) {
                // out = x + gate * (acc + bias + skip)
                int bb = row >> 10;
                float g0 = __ldg(adaP + bb * THREED + 2 * Dd + col);
                float g1 = __ldg(adaP + bb * THREED + 2 * Dd + col + 1);
                size_t i0 = (size_t)row * Dd + col;
                size_t i1 = (size_t)(row + 8) * Dd + col;
                v0 = __ldg(xP + i0)     + g0 * (v0 + __ldg(skipP + i0));
                v1 = __ldg(xP + i0 + 1) + g1 * (v1 + __ldg(skipP + i0 + 1));
                v2 = __ldg(xP + i1)     + g0 * (v2 + __ldg(skipP + i1));
                v3 = __ldg(xP + i1 + 1) + g1 * (v3 + __ldg(skipP + i1 + 1));
            }
            if (col < nRound) {
                v0 = roundtf(v0); v1 = roundtf(v1);
                v2 = roundtf(v2); v3 = roundtf(v3);
            }
            float2 lo = make_float2(v0, v1), hi = make_float2(v2, v3);
            *(float2*)&Cp[(size_t)row * ldc + col] = lo;
            *(float2*)&Cp[(size_t)(row + 8) * ldc + col] = hi;
        }
    }
}

// ---------------- split-K reduction for both branches (rounds output) ------------
__global__ void reduce_splitk2(const float* __restrict__ part,
                               float* __restrict__ out1,
                               float* __restrict__ out2, int n)
{
    int i = blockIdx.x * blockDim.x + threadIdx.x;
    if (i < 2 * n) {
        int br = (i >= n);
        int j  = i - br * n;
        const float* p = part + (size_t)(br * KSPLIT) * n + j;
        float s = 0.0f;
#pragma unroll
        for (int z = 0; z < KSPLIT; z++) s += p[(size_t)z * n];
        float v = roundtf(s);
        if (br) out2[j] = v; else out1[j] = v;
    }
}

// ---------------- ada: one warp computes both batch outputs ----------------------
__global__ __launch_bounds__(256) void ada_kernel(
    const float* __restrict__ c, const float* __restrict__ Wada,
    const float* __restrict__ bada, float* __restrict__ ada)
{
    int w    = (blockIdx.x * blockDim.x + threadIdx.x) >> 5;   // 0..3071
    int lane = threadIdx.x & 31;

    const float4* wp  = (const float4*)(Wada + (size_t)w * 2 * Dd);
    const float4* c0p = (const float4*)c;
    const float4* c1p = (const float4*)(c + 2 * Dd);
    float s0 = 0.0f, s1 = 0.0f;
#pragma unroll
    for (int it = 0; it < 16; it++) {
        float4 wv = __ldg(&wp[lane + it * 32]);
        float4 a0 = __ldg(&c0p[lane + it * 32]);
        float4 a1 = __ldg(&c1p[lane + it * 32]);
        s0 += siluf(a0.x) * wv.x + siluf(a0.y) * wv.y
            + siluf(a0.z) * wv.z + siluf(a0.w) * wv.w;
        s1 += siluf(a1.x) * wv.x + siluf(a1.y) * wv.y
            + siluf(a1.z) * wv.z + siluf(a1.w) * wv.w;
    }
#pragma unroll
    for (int off = 16; off; off >>= 1) {
        s0 += __shfl_xor_sync(0xffffffffu, s0, off);
        s1 += __shfl_xor_sync(0xffffffffu, s1, off);
    }
    if (lane == 0) {
        float bv = __ldg(bada + w);
        ada[w] = s0 + bv;
        ada[THREED + w] = s1 + bv;
    }
}

// ---------------- fused LN1 + modulate(+store skip) + LN2 (xn rounded) -----------
__global__ __launch_bounds__(256) void ln_mod_kernel(
    const float* __restrict__ x,
    const float* __restrict__ g1, const float* __restrict__ b1,
    const float* __restrict__ g2, const float* __restrict__ b2,
    const float* __restrict__ ada,
    float* __restrict__ skip, float* __restrict__ xn)
{
    __shared__ float sh[8];
    const int row = blockIdx.x;
    const int b = row >> 10;
    const float* xr = x + (size_t)row * Dd;

    float v[4];
#pragma unroll
    for (int j = 0; j < 4; j++) v[j] = xr[threadIdx.x + j * 256];

    float s1 = 0.0f, s2 = 0.0f;
#pragma unroll
    for (int j = 0; j < 4; j++) { s1 += v[j]; s2 += v[j] * v[j]; }
    s1 = blockReduceSum(s1, sh);
    s2 = blockReduceSum(s2, sh);
    float m  = s1 * (1.0f / Dd);
    float rs = rsqrtf(s2 * (1.0f / Dd) - m * m + 1e-5f);

    float t[4];
    s1 = 0.0f; s2 = 0.0f;
#pragma unroll
    for (int j = 0; j < 4; j++) {
        int d = threadIdx.x + j * 256;
        float tt = (v[j] - m) * rs * g1[d] + b1[d];
        tt = tt * (1.0f + ada[b * THREED + Dd + d]) + ada[b * THREED + d];
        t[j] = tt;
        skip[(size_t)row * Dd + d] = tt;
        s1 += tt; s2 += tt * tt;
    }
    s1 = blockReduceSum(s1, sh);
    s2 = blockReduceSum(s2, sh);
    float m2  = s1 * (1.0f / Dd);
    float rs2 = rsqrtf(s2 * (1.0f / Dd) - m2 * m2 + 1e-5f);

#pragma unroll
    for (int j = 0; j < 4; j++) {
        int d = threadIdx.x + j * 256;
        xn[(size_t)row * Dd + d] = roundtf((t[j] - m2) * rs2 * g2[d] + b2[d]);
    }
}

// ---------------- SMEM-staged selective scan -------------------------------------
__global__ __launch_bounds__(256) void scan_smem_kernel(
    const float* __restrict__ de1, const float* __restrict__ de2,
    const float* __restrict__ z12, int ldz,
    const float* __restrict__ dbc1, const float* __restrict__ dbc2,
    const float* __restrict__ Alog1, const float* __restrict__ Alog2,
    const float* __restrict__ Dp1, const float* __restrict__ Dp2,
    float* __restrict__ gg1, float* __restrict__ gg2)
{
    __shared__ float deS[2][SCH][16];
    __shared__ float zS [2][SCH][16];
    __shared__ float bcS[2][SCH][32];
    __shared__ float ggS[SCH][16];

    const int tid = threadIdx.x;
    const int u   = tid >> 4;
    const int n   = tid & 15;

    const int bx = blockIdx.x;         // 0..511
    const int et = bx & 127;
    const int b  = (bx >> 7) & 1;
    const int br = bx >> 8;
    const int e0 = et * 16;

    const float* de   = br ? de2  : de1;
    const float* z    = z12 + (br ? Ee : 0);
    const float* dbc  = br ? dbc2 : dbc1;
    const float* Alog = br ? Alog2 : Alog1;
    const float* Dp   = br ? Dp2  : Dp1;
    float*       gg   = br ? gg2  : gg1;

    const int e = e0 + u;
    const float A_n  = -__expf(Alog[e * Nn + n]);
    const float Dp_e = Dp[e];

    const size_t rowBase = (size_t)b * Ss;

    uint32_t deSm = (uint32_t)__cvta_generic_to_shared(&deS[0][0][0]);
    uint32_t zSm  = (uint32_t)__cvta_generic_to_shared(&zS[0][0][0]);
    uint32_t bcSm = (uint32_t)__cvta_generic_to_shared(&bcS[0][0][0]);

    const int lr  = tid >> 2;
    const int lp  = (tid & 3) * 4;
    const int br0 = (tid * 2) >> 3;
    const int bp0 = ((tid * 2) & 7) * 4;
    const int br1 = (tid * 2 + 1) >> 3;
    const int bp1 = ((tid * 2 + 1) & 7) * 4;

    auto loadChunk = [&](int c, int buf) {
        int s = br ? (Ss - 1 - (c * SCH + lr)) : (c * SCH + lr);
        const float* gd = de + (rowBase + s) * Ee + e0 + lp;
        const float* gz = z  + (rowBase + s) * (size_t)ldz + e0 + lp;
        CP16F(deSm + (uint32_t)((buf * SCH + lr) * 16 + lp) * 4u, gd);
        CP16F(zSm  + (uint32_t)((buf * SCH + lr) * 16 + lp) * 4u, gz);
        int s0 = br ? (Ss - 1 - (c * SCH + br0)) : (c * SCH + br0);
        int s1b = br ? (Ss - 1 - (c * SCH + br1)) : (c * SCH + br1);
        const float* g0 = dbc + (rowBase + s0) * DBCW + Rr + bp0;
        const float* g1 = dbc + (rowBase + s1b) * DBCW + Rr + bp1;
        CP16F(bcSm + (uint32_t)((buf * SCH + br0) * 32 + bp0) * 4u, g0);
        CP16F(bcSm + (uint32_t)((buf * SCH + br1) * 32 + bp1) * 4u, g1);
    };

    loadChunk(0, 0);
    asm volatile("cp.async.commit_group;");

    float h = 0.0f;

    for (int c = 0; c < NCH; c++) {
        if (c + 1 < NCH) {
            loadChunk(c + 1, (c + 1) & 1);
            asm volatile("cp.async.commit_group;");
            asm volatile("cp.async.wait_group 1;");
        } else {
            asm volatile("cp.async.wait_group 0;");
        }
        __syncthreads();

        const int buf = c & 1;
#pragma unroll 8
        for (int cs = 0; cs < SCH; cs++) {
            float dlt = deS[buf][cs][u];
            float uu  = zS[buf][cs][u];
            float Bv  = bcS[buf][cs][n];
            float Cv  = bcS[buf][cs][16 + n];

            h = __expf(dlt * A_n) * h + dlt * Bv * uu;
            float y = h * Cv;
            y += __shfl_xor_sync(0xffffffffu, y, 8);
            y += __shfl_xor_sync(0xffffffffu, y, 4);
            y += __shfl_xor_sync(0xffffffffu, y, 2);
            y += __shfl_xor_sync(0xffffffffu, y, 1);
            if (n == 0) ggS[cs][u] = y + uu * Dp_e;
        }
        __syncthreads();

        {
            int r = tid >> 2, p = (tid & 3) * 4;
            int s = br ? (Ss - 1 - (c * SCH + r)) : (c * SCH + r);
            *(float4*)&gg[(rowBase + s) * Ee + e0 + p] = *(float4*)&ggS[r][p];
        }
    }
}

// ---------------- acmb = silu(mx) * (gg1 + gg2), rounded --------------------------
__global__ void combine_kernel(const float4* __restrict__ mzx,
                               const float4* __restrict__ gg1,
                               const float4* __restrict__ gg2,
                               float4* __restrict__ a, int n4)
{
    int i = blockIdx.x * blockDim.x + threadIdx.x;
    if (i < n4) {
        int row  = i >> 9;              // / (Ee/4)
        int col4 = i & 511;
        float4 m = mzx[row * 1024 + 512 + col4];   // mx half (ld=4096 floats)
        float4 p = gg1[i], q = gg2[i], r;
        r.x = roundtf(siluf(m.x) * (p.x + q.x));
        r.y = roundtf(siluf(m.y) * (p.y + q.y));
        r.z = roundtf(siluf(m.z) * (p.z + q.z));
        r.w = roundtf(siluf(m.w) * (p.w + q.w));
        a[i] = r;
    }
}

// ---------------- host launcher ----------------------------------------------------
extern "C" void kernel_launch(void* const* d_in, const int* in_sizes, int n_in,
                              void* d_out, int out_size)
{
    const float* x     = (const float*)d_in[0];
    const float* c     = (const float*)d_in[1];
    const float* n1g   = (const float*)d_in[3];
    const float* n1b   = (const float*)d_in[4];
    const float* n2g   = (const float*)d_in[5];
    const float* n2b   = (const float*)d_in[6];
    const float* Wx    = (const float*)d_in[7];
    const float* bx    = (const float*)d_in[8];
    const float* Wz    = (const float*)d_in[9];
    const float* bz    = (const float*)d_in[10];
    const float* Wf    = (const float*)d_in[11];
    const float* bf    = (const float*)d_in[12];
    const float* Wada  = (const float*)d_in[13];
    const float* bada  = (const float*)d_in[14];
    const float* Wc1   = (const float*)d_in[15];
    const float* bc1   = (const float*)d_in[16];
    const float* Wc2   = (const float*)d_in[17];
    const float* bc2   = (const float*)d_in[18];
    const float* Wdbc1 = (const float*)d_in[19];
    const float* Wdt1  = (const float*)d_in[20];
    const float* bdt1  = (const float*)d_in[21];
    const float* Alog1 = (const float*)d_in[22];
    const float* Dp1   = (const float*)d_in[23];
    const float* Wdbc2 = (const float*)d_in[24];
    const float* Wdt2  = (const float*)d_in[25];
    const float* bdt2  = (const float*)d_in[26];
    const float* Alog2 = (const float*)d_in[27];
    const float* Dp2   = (const float*)d_in[28];
    float* out = (float*)d_out;

    float *ada, *skip, *xn, *mzx, *z12, *dbc1, *dbc2;
    float *de1, *de2, *gg1, *gg2, *acmb, *part;
    float *wzx, *wc12, *wdbc1, *wdbc2, *wdt1, *wdt2, *wf, *bzx, *bc12;
    cudaGetSymbolAddress((void**)&ada,  g_ada);
    cudaGetSymbolAddress((void**)&skip, g_skip);
    cudaGetSymbolAddress((void**)&xn,   g_xn);
    cudaGetSymbolAddress((void**)&mzx,  g_mzx);
    cudaGetSymbolAddress((void**)&z12,  g_z12);
    cudaGetSymbolAddress((void**)&dbc1, g_dbc1);
    cudaGetSymbolAddress((void**)&dbc2, g_dbc2);
    cudaGetSymbolAddress((void**)&de1,  g_del1);
    cudaGetSymbolAddress((void**)&de2,  g_del2);
    cudaGetSymbolAddress((void**)&gg1,  g_gg1);
    cudaGetSymbolAddress((void**)&gg2,  g_gg2);
    cudaGetSymbolAddress((void**)&acmb, g_acmb);
    cudaGetSymbolAddress((void**)&part, g_part);
    cudaGetSymbolAddress((void**)&wzx,   g_wzx);
    cudaGetSymbolAddress((void**)&wc12,  g_wc12);
    cudaGetSymbolAddress((void**)&wdbc1, g_wdbc1);
    cudaGetSymbolAddress((void**)&wdbc2, g_wdbc2);
    cudaGetSymbolAddress((void**)&wdt1,  g_wdt1);
    cudaGetSymbolAddress((void**)&wdt2,  g_wdt2);
    cudaGetSymbolAddress((void**)&wf,    g_wf);
    cudaGetSymbolAddress((void**)&bzx,   g_bzx);
    cudaGetSymbolAddress((void**)&bc12,  g_bc12);

    const int SMEM = 98304;   // 3-stage pipeline: 2 x 3 x 16KB
    cudaFuncSetAttribute(gemm_tf32<0>, cudaFuncAttributeMaxDynamicSharedMemorySize, SMEM);
    cudaFuncSetAttribute(gemm_tf32<1>, cudaFuncAttributeMaxDynamicSharedMemorySize, SMEM);
    cudaFuncSetAttribute(gemm_tf32<3>, cudaFuncAttributeMaxDynamicSharedMemorySize, SMEM);

    // 1. fused weight round + bias concat (one launch)
    {
        RoundJobs jb;
        const float* srcs[NSEG] = { Wz, Wx, Wc1, Wc2, Wdbc1, Wdbc2, Wdt1, Wdt2, Wf,
                                    bz, bx, bc1, bc2 };
        float* dsts[NSEG] = { wzx, wzx + (size_t)Ee * Dd,
                              wc12, wc12 + (size_t)Ee * Ee,
                              wdbc1, wdbc2, wdt1, wdt2, wf,
                              bzx, bzx + Ee, bc12, bc12 + Ee };
        int sizes4[NSEG] = { Ee * Dd / 4, Ee * Dd / 4, Ee * Ee / 4, Ee * Ee / 4,
                             DBCW * Ee / 4, DBCW * Ee / 4, Ee * Rr / 4, Ee * Rr / 4,
                             Dd * Ee / 4, Ee / 4, Ee / 4, Ee / 4, Ee / 4 };
        int rnds[NSEG] = { 1,1,1,1,1,1,1,1,1, 0,0,0,0 };
        int off = 0;
        for (int s = 0; s < NSEG; s++) {
            jb.src[s] = (const float4*)srcs[s];
            jb.dst[s] = (float4*)dsts[s];
            jb.off[s] = off;
            jb.rnd[s] = rnds[s];
            off += sizes4[s];
        }
        jb.off[NSEG] = off;
        round_all_kernel<<<(off + 255) / 256, 256>>>(jb, off);
    }

    // 2. ada = silu(c) @ Wada^T + bada  (one warp -> both batch rows)
    ada_kernel<<<384, 256>>>(c, Wada, bada, ada);

    // 3. LN1 + modulate (-> skip) + LN2 (-> xn, rounded)
    ln_mod_kernel<<<BSr, 256>>>(x, n1g, n1b, n2g, n2b, ada, skip, xn);

    // 4. merged mz|mx  [2048, 4096] K=1024
    gemm_tf32<0><<<dim3(2 * Ee / 128, BSr / 128, 1), 256, SMEM>>>(
        xn, Dd, wzx, Dd, bzx, mzx, 2 * Ee, BSr, 2 * Ee, Dd, Ee, 1, 0,
        nullptr, nullptr, nullptr, nullptr, nullptr, nullptr, nullptr);

    // 5. merged z1|z2  [2048, 4096] K=2048 (A = mz half of mzx, lda=4096)
    gemm_tf32<0><<<dim3(2 * Ee / 128, BSr / 128, 1), 256, SMEM>>>(
        mzx, 2 * Ee, wc12, Ee, bc12, z12, 2 * Ee, BSr, 2 * Ee, Ee, 2 * Ee, 1, 0,
        nullptr, nullptr, nullptr, nullptr, nullptr, nullptr, nullptr);

    // 6. dbc (both branches, split-K=8, one launch: grid.z = 16)
    gemm_tf32<0><<<dim3(1, BSr / 128, 2 * KSPLIT), 256, SMEM>>>(
        z12, 2 * Ee, wdbc1, Ee, nullptr, part, DBCW, BSr, DBCW, Ee, 0,
        KSPLIT, BSr * DBCW,
        z12 + Ee, wdbc2, nullptr, nullptr, nullptr, nullptr, nullptr);

    // 7. reduce both branches -> dbc1, dbc2 (rounded)
    reduce_splitk2<<<(2 * BSr * DBCW + 255) / 256, 256>>>(part, dbc1, dbc2, BSr * DBCW);

    // 8. delta (both branches, one launch: grid.z = 2), softplus epilogue
    gemm_tf32<1><<<dim3(Ee / 128, BSr / 128, 2), 256, SMEM>>>(
        dbc1, DBCW, wdt1, Rr, bdt1, de1, Ee, BSr, Ee, Rr, 0, 1, 0,
        dbc2, wdt2, bdt2, de2, nullptr, nullptr, nullptr);

    // 9. both selective scans, SMEM-staged
    scan_smem_kernel<<<512, 256>>>(de1, de2, z12, 2 * Ee, dbc1, dbc2,
                                   Alog1, Alog2, Dp1, Dp2, gg1, gg2);

    // 10. acmb = silu(mx) * (gg1 + gg2), rounded
    combine_kernel<<<(BSr * Ee / 4 + 255) / 256, 256>>>(
        (const float4*)mzx, (const float4*)gg1, (const float4*)gg2,
        (float4*)acmb, BSr * Ee / 4);

    // 11. fused final GEMM: out = x + gate * (acmb @ Wf^T + bf + skip)
    gemm_tf32<3><<<dim3(Dd / 128, BSr / 128, 1), 256, SMEM>>>(
        acmb, Ee, wf, Ee, bf, out, Dd, BSr, Dd, Ee, 0, 1, 0,
        nullptr, nullptr, nullptr, nullptr, x, skip, ada);
}

// round 13
// speedup vs baseline: 1.3736x; 1.3255x over previous
#include <cuda_runtime.h>
#include <cuda_fp16.h>
#include <math.h>
#include <stdint.h>

// Problem constants
#define Bb   2
#define Ss   1024
#define Dd   1024
#define Ee   2048
#define Nn   16
#define Rr   64
#define BSr  (Bb * Ss)          // 2048 rows
#define DBCW (Rr + 2 * Nn)      // 96
#define THREED (3 * Dd)         // 3072
#define KSPLIT 8
#define SCH  64                 // scan chunk (steps per SMEM stage)
#define NCH  (Ss / SCH)         // 16 chunks

// ---------------- scratch (device globals; no allocation in kernel_launch) ----
__device__ float  g_ada  [Bb * THREED];
__device__ float  g_skip [BSr * Dd];
__device__ __half g_xn   [BSr * Dd];
__device__ __half g_mzx  [BSr * 2 * Ee];     // mz | mx  (ld = 4096 halves)
__device__ __half g_z12  [BSr * 2 * Ee];     // z1 | z2  (ld = 4096 halves)
__device__ __half g_dbc1 [BSr * DBCW];
__device__ __half g_dbc2 [BSr * DBCW];
__device__ __half g_del1 [BSr * Ee];
__device__ __half g_del2 [BSr * Ee];
__device__ float  g_gg1  [BSr * Ee];
__device__ float  g_gg2  [BSr * Ee];
__device__ __half g_acmb [BSr * Ee];
__device__ float  g_part [2 * KSPLIT * BSr * DBCW];
// fp16 weights / fp32 concat biases
__device__ __half g_wzx  [2 * Ee * Dd];      // [Wz ; Wx]
__device__ __half g_wc12 [2 * Ee * Ee];      // [Wc1 ; Wc2]
__device__ __half g_wdbc1[DBCW * Ee];
__device__ __half g_wdbc2[DBCW * Ee];
__device__ __half g_wdt1 [Ee * Rr];
__device__ __half g_wdt2 [Ee * Rr];
__device__ __half g_wf   [Dd * Ee];
__device__ float  g_bzx  [2 * Ee];           // [bz ; bx]
__device__ float  g_bc12 [2 * Ee];           // [bc1 ; bc2]

// ---------------- helpers -----------------------------------------------------
__device__ __forceinline__ float siluf(float v) { return v / (1.0f + __expf(-v)); }
__device__ __forceinline__ float softplusf(float v) {
    return (v > 20.0f) ? v : log1pf(__expf(v));
}
__device__ __forceinline__ void mma_f16(float* c, const uint32_t* a, const uint32_t* b) {
    asm volatile(
        "mma.sync.aligned.m16n8k16.row.col.f32.f16.f16.f32 "
        "{%0,%1,%2,%3},{%4,%5,%6,%7},{%8,%9},{%0,%1,%2,%3};"
        : "+f"(c[0]), "+f"(c[1]), "+f"(c[2]), "+f"(c[3])
        : "r"(a[0]), "r"(a[1]), "r"(a[2]), "r"(a[3]), "r"(b[0]), "r"(b[1]));
}
#define CP16(dst, src, sz) \
    asm volatile("cp.async.cg.shared.global [%0], [%1], 16, %2;" \
                 :: "r"(dst), "l"(src), "r"(sz))
#define CP16F(dst, src) \
    asm volatile("cp.async.cg.shared.global [%0], [%1], 16;" \
                 :: "r"(dst), "l"(src))

// fragment load from swizzled half tile: row r (32 halves/row), 4B-word w (0..15)
__device__ __forceinline__ uint32_t fragld(const __half* base, int r, int w) {
    int ch = (w >> 2) ^ ((r >> 1) & 3);
    return *(const uint32_t*)(base + r * 32 + ch * 8 + (w & 3) * 2);
}

__device__ __forceinline__ float blockReduceSum(float v, float* sh) {
    int lane = threadIdx.x & 31, wid = threadIdx.x >> 5;
#pragma unroll
    for (int o = 16; o; o >>= 1) v += __shfl_xor_sync(0xffffffffu, v, o);
    __syncthreads();
    if (lane == 0) sh[wid] = v;
    __syncthreads();
    if (wid == 0) {
        v = (lane < 8) ? sh[lane] : 0.0f;
#pragma unroll
        for (int o = 4; o; o >>= 1) v += __shfl_xor_sync(0xffffffffu, v, o);
        if (lane == 0) sh[0] = v;
    }
    __syncthreads();
    return sh[0];
}

// ---------------- fused weight convert (fp32->fp16) + bias concat ---------------
#define NSEG 13
struct CvtJobs {
    const float4* src[NSEG];
    void*         dst[NSEG];
    int           off[NSEG + 1];   // start (in float4 units of src)
    int           cvt[NSEG];       // 1 = convert to half, 0 = fp32 copy
};

__global__ void cvt_all_kernel(CvtJobs jb, int total4) {
    int i = blockIdx.x * blockDim.x + threadIdx.x;
    if (i >= total4) return;
    int s = 0;
#pragma unroll
    for (int k = 1; k < NSEG; k++) if (i >= jb.off[k]) s = k;
    int j = i - jb.off[s];
    float4 v = jb.src[s][j];
    if (jb.cvt[s]) {
        __half2 h0 = __floats2half2_rn(v.x, v.y);
        __half2 h1 = __floats2half2_rn(v.z, v.w);
        uint2 u = make_uint2(*(uint32_t*)&h0, *(uint32_t*)&h1);
        *(uint2*)((char*)jb.dst[s] + (size_t)j * 8) = u;
    } else {
        ((float4*)jb.dst[s])[j] = v;
    }
}

// ---------------- fp16 tensor-core GEMM (templated epilogue/output) -------------
// C[M,N] = A[M,K] * W[N,K]^T (+bias, +epi). Tile 128x128x32, 256 threads,
// 8 warps (2x4), warp tile 64x32, mma m16n8k16 f16 (fp32 accum). 3-stage
// cp.async pipeline, issue-before-wait, XOR-swizzled half SMEM.
// EPI: 0 none, 1 softplus, 3 fused ViM final. HOUT: 1 = fp16 output, 0 = fp32.
// Batching: blockIdx.z in [0, splitK * nBranch); branch = z / splitK selects
// (A2,W2,bias2,C2). Output at C + z*partStride (bias only when splitK == 1).
template <int EPI, int HOUT>
__global__ __launch_bounds__(256, 2) void gemm_f16(
    const __half* __restrict__ A_, int lda,
    const __half* __restrict__ W_, int ldb,
    const float* __restrict__ bias_,
    void* __restrict__ C_, int ldc,
    int M, int N, int K, int splitK, int partStride,
    const __half* A2, const __half* W2, const float* bias2, void* C2,
    const float* xP, const float* skipP, const float* adaP)
{
    extern __shared__ __half smh[];
    __half* As = smh;             // [3][128*32] halves (8KB/stage)
    __half* Bs = smh + 12288;     // [3][128*32]

    const __half* A = A_;
    const __half* W = W_;
    const float* bias = bias_;
    void* C = C_;

    const int bz = blockIdx.z;
    const int br = bz / splitK;
    const int kz = bz % splitK;
    if (br == 1) { A = A2; W = W2; bias = bias2; if (C2) C = C2; }

    const int tid  = threadIdx.x;
    const int wid  = tid >> 5, lane = tid & 31;
    const int wm   = wid >> 2, wn = wid & 3;
    const int grp  = lane >> 2, tig = lane & 3;
    const int bm   = blockIdx.y * 128, bn = blockIdx.x * 128;
    const int klen   = K / splitK;
    const int kstart = kz * klen;
    const int ntile  = klen >> 5;

    float acc[4][4][4];
#pragma unroll
    for (int i = 0; i < 4; i++)
#pragma unroll
        for (int j = 0; j < 4; j++)
#pragma unroll
            for (int r = 0; r < 4; r++) acc[i][j][r] = 0.0f;

    // cp.async roles: 2 chunks/operand/thread (tile = 128 rows x 4 x 16B chunks)
    uint32_t aSm[2], bSm[2], bSz[2];
    const __half* aP[2];
    const __half* bP[2];
    const uint32_t sA = (uint32_t)__cvta_generic_to_shared(As);
    const uint32_t sB = (uint32_t)__cvta_generic_to_shared(Bs);
#pragma unroll
    for (int i = 0; i < 2; i++) {
        int f = tid + i * 256;
        int m = f >> 2, cch = f & 3;
        int csw = cch ^ ((m >> 1) & 3);
        aSm[i] = sA + (uint32_t)(m * 64 + csw * 16);
        bSm[i] = sB + (uint32_t)(m * 64 + csw * 16);
        aP[i]  = A + (size_t)(bm + m) * lda + kstart + cch * 8;
        int brow = bn + m;
        bSz[i] = (brow < N) ? 16u : 0u;
        if (brow >= N) brow = N - 1;
        bP[i]  = W + (size_t)brow * ldb + kstart + cch * 8;
    }

    // prologue: stages 0 and 1
#pragma unroll
    for (int st = 0; st < 2; st++) {
        if (st < ntile) {
            const uint32_t so = (uint32_t)st * 8192u;
#pragma unroll
            for (int i = 0; i < 2; i++) {
                CP16(aSm[i] + so, aP[i], 16u);
                CP16(bSm[i] + so, bP[i], bSz[i]);
                aP[i] += 32; bP[i] += 32;
            }
            asm volatile("cp.async.commit_group;");
        }
    }

    for (int t = 0; t < ntile; t++) {
        if (t + 2 < ntile) {
            const int st = (t + 2) % 3;
            const uint32_t so = (uint32_t)st * 8192u;
#pragma unroll
            for (int i = 0; i < 2; i++) {
                CP16(aSm[i] + so, aP[i], 16u);
                CP16(bSm[i] + so, bP[i], bSz[i]);
                aP[i] += 32; bP[i] += 32;
            }
            asm volatile("cp.async.commit_group;");
            asm volatile("cp.async.wait_group 2;");
        } else if (t + 1 < ntile) {
            asm volatile("cp.async.wait_group 1;");
        } else {
            asm volatile("cp.async.wait_group 0;");
        }
        __syncthreads();

        const __half* Ah = As + (t % 3) * 4096;
        const __half* Bh = Bs + (t % 3) * 4096;
#pragma unroll
        for (int ks = 0; ks < 2; ks++) {
            const int w0 = tig + ks * 8;
            const int w1 = tig + 4 + ks * 8;
            uint32_t af[4][4], bf[4][2];
#pragma unroll
            for (int mt = 0; mt < 4; mt++) {
                int r = wm * 64 + mt * 16 + grp;
                af[mt][0] = fragld(Ah, r,     w0);
                af[mt][1] = fragld(Ah, r + 8, w0);
                af[mt][2] = fragld(Ah, r,     w1);
                af[mt][3] = fragld(Ah, r + 8, w1);
            }
#pragma unroll
            for (int nt = 0; nt < 4; nt++) {
                int n = wn * 32 + nt * 8 + grp;
                bf[nt][0] = fragld(Bh, n, w0);
                bf[nt][1] = fragld(Bh, n, w1);
            }
#pragma unroll
            for (int mt = 0; mt < 4; mt++)
#pragma unroll
                for (int nt = 0; nt < 4; nt++)
                    mma_f16(acc[mt][nt], af[mt], bf[nt]);
        }
        __syncthreads();
    }

    const bool doBias = (bias != nullptr) && (splitK == 1);
#pragma unroll
    for (int mt = 0; mt < 4; mt++) {
#pragma unroll
        for (int nt = 0; nt < 4; nt++) {
            int row = bm + wm * 64 + mt * 16 + grp;
            int col = bn + wn * 32 + nt * 8 + tig * 2;
            if (col >= N) continue;
            float b0 = doBias ? __ldg(bias + col) : 0.0f;
            float b1 = doBias ? __ldg(bias + col + 1) : 0.0f;
            float v0 = acc[mt][nt][0] + b0, v1 = acc[mt][nt][1] + b1;
            float v2 = acc[mt][nt][2] + b0, v3 = acc[mt][nt][3] + b1;
            if (EPI == 1) {
                v0 = softplusf(v0); v1 = softplusf(v1);
                v2 = softplusf(v2); v3 = softplusf(v3);
            } else if (EPI == 3) {
                int bb = row >> 10;
                float g0 = __ldg(adaP + bb * THREED + 2 * Dd + col);
                float g1 = __ldg(adaP + bb * THREED + 2 * Dd + col + 1);
                size_t i0 = (size_t)row * Dd + col;
                size_t i1 = (size_t)(row + 8) * Dd + col;
                v0 = __ldg(xP + i0)     + g0 * (v0 + __ldg(skipP + i0));
                v1 = __ldg(xP + i0 + 1) + g1 * (v1 + __ldg(skipP + i0 + 1));
                v2 = __ldg(xP + i1)     + g0 * (v2 + __ldg(skipP + i1));
                v3 = __ldg(xP + i1 + 1) + g1 * (v3 + __ldg(skipP + i1 + 1));
            }
            if (HOUT) {
                __half* Ch = (__half*)C + (size_t)bz * partStride;
                __half2 lo = __floats2half2_rn(v0, v1);
                __half2 hi = __floats2half2_rn(v2, v3);
                *(__half2*)&Ch[(size_t)row * ldc + col] = lo;
                *(__half2*)&Ch[(size_t)(row + 8) * ldc + col] = hi;
            } else {
                float* Cf = (float*)C + (size_t)bz * partStride;
                *(float2*)&Cf[(size_t)row * ldc + col] = make_float2(v0, v1);
                *(float2*)&Cf[(size_t)(row + 8) * ldc + col] = make_float2(v2, v3);
            }
        }
    }
}

// ---------------- split-K reduction (fp32 partials -> fp16 out) ------------------
__global__ void reduce_splitk2(const float* __restrict__ part,
                               __half* __restrict__ out1,
                               __half* __restrict__ out2, int n)
{
    int i = blockIdx.x * blockDim.x + threadIdx.x;
    if (i < 2 * n) {
        int br = (i >= n);
        int j  = i - br * n;
        const float* p = part + (size_t)(br * KSPLIT) * n + j;
        float s = 0.0f;
#pragma unroll
        for (int z = 0; z < KSPLIT; z++) s += p[(size_t)z * n];
        __half v = __float2half_rn(s);
        if (br) out2[j] = v; else out1[j] = v;
    }
}

// ---------------- ada: one warp computes both batch outputs ----------------------
__global__ __launch_bounds__(256) void ada_kernel(
    const float* __restrict__ c, const float* __restrict__ Wada,
    const float* __restrict__ bada, float* __restrict__ ada)
{
    int w    = (blockIdx.x * blockDim.x + threadIdx.x) >> 5;   // 0..3071
    int lane = threadIdx.x & 31;

    const float4* wp  = (const float4*)(Wada + (size_t)w * 2 * Dd);
    const float4* c0p = (const float4*)c;
    const float4* c1p = (const float4*)(c + 2 * Dd);
    float s0 = 0.0f, s1 = 0.0f;
#pragma unroll
    for (int it = 0; it < 16; it++) {
        float4 wv = __ldg(&wp[lane + it * 32]);
        float4 a0 = __ldg(&c0p[lane + it * 32]);
        float4 a1 = __ldg(&c1p[lane + it * 32]);
        s0 += siluf(a0.x) * wv.x + siluf(a0.y) * wv.y
            + siluf(a0.z) * wv.z + siluf(a0.w) * wv.w;
        s1 += siluf(a1.x) * wv.x + siluf(a1.y) * wv.y
            + siluf(a1.z) * wv.z + siluf(a1.w) * wv.w;
    }
#pragma unroll
    for (int off = 16; off; off >>= 1) {
        s0 += __shfl_xor_sync(0xffffffffu, s0, off);
        s1 += __shfl_xor_sync(0xffffffffu, s1, off);
    }
    if (lane == 0) {
        float bv = __ldg(bada + w);
        ada[w] = s0 + bv;
        ada[THREED + w] = s1 + bv;
    }
}

// ---------------- fused LN1 + modulate(+store skip) + LN2 (xn -> fp16) -----------
__global__ __launch_bounds__(256) void ln_mod_kernel(
    const float* __restrict__ x,
    const float* __restrict__ g1, const float* __restrict__ b1,
    const float* __restrict__ g2, const float* __restrict__ b2,
    const float* __restrict__ ada,
    float* __restrict__ skip, __half* __restrict__ xn)
{
    __shared__ float sh[8];
    const int row = blockIdx.x;
    const int b = row >> 10;
    const float* xr = x + (size_t)row * Dd;

    float v[4];
#pragma unroll
    for (int j = 0; j < 4; j++) v[j] = xr[threadIdx.x + j * 256];

    float s1 = 0.0f, s2 = 0.0f;
#pragma unroll
    for (int j = 0; j < 4; j++) { s1 += v[j]; s2 += v[j] * v[j]; }
    s1 = blockReduceSum(s1, sh);
    s2 = blockReduceSum(s2, sh);
    float m  = s1 * (1.0f / Dd);
    float rs = rsqrtf(s2 * (1.0f / Dd) - m * m + 1e-5f);

    float t[4];
    s1 = 0.0f; s2 = 0.0f;
#pragma unroll
    for (int j = 0; j < 4; j++) {
        int d = threadIdx.x + j * 256;
        float tt = (v[j] - m) * rs * g1[d] + b1[d];
        tt = tt * (1.0f + ada[b * THREED + Dd + d]) + ada[b * THREED + d];
        t[j] = tt;
        skip[(size_t)row * Dd + d] = tt;
        s1 += tt; s2 += tt * tt;
    }
    s1 = blockReduceSum(s1, sh);
    s2 = blockReduceSum(s2, sh);
    float m2  = s1 * (1.0f / Dd);
    float rs2 = rsqrtf(s2 * (1.0f / Dd) - m2 * m2 + 1e-5f);

#pragma unroll
    for (int j = 0; j < 4; j++) {
        int d = threadIdx.x + j * 256;
        xn[(size_t)row * Dd + d] = __float2half_rn((t[j] - m2) * rs2 * g2[d] + b2[d]);
    }
}

// ---------------- SMEM-staged selective scan (fp16 inputs) ------------------------
__global__ __launch_bounds__(256) void scan_smem_kernel(
    const __half* __restrict__ de1, const __half* __restrict__ de2,
    const __half* __restrict__ z12, int ldz,
    const __half* __restrict__ dbc1, const __half* __restrict__ dbc2,
    const float* __restrict__ Alog1, const float* __restrict__ Alog2,
    const float* __restrict__ Dp1, const float* __restrict__ Dp2,
    float* __restrict__ gg1, float* __restrict__ gg2)
{
    __shared__ __half deS[2][SCH][16];
    __shared__ __half zS [2][SCH][16];
    __shared__ __half bcS[2][SCH][32];
    __shared__ float  ggS[SCH][16];

    const int tid = threadIdx.x;
    const int u   = tid >> 4;
    const int n   = tid & 15;

    const int bx = blockIdx.x;         // 0..511
    const int et = bx & 127;
    const int b  = (bx >> 7) & 1;
    const int br = bx >> 8;
    const int e0 = et * 16;

    const __half* de   = br ? de2  : de1;
    const __half* z    = z12 + (br ? Ee : 0);
    const __half* dbc  = br ? dbc2 : dbc1;
    const float* Alog  = br ? Alog2 : Alog1;
    const float* Dp    = br ? Dp2  : Dp1;
    float*       gg    = br ? gg2  : gg1;

    const int e = e0 + u;
    const float A_n  = -__expf(Alog[e * Nn + n]);
    const float Dp_e = Dp[e];

    const size_t rowBase = (size_t)b * Ss;

    uint32_t deSm = (uint32_t)__cvta_generic_to_shared(&deS[0][0][0]);
    uint32_t zSm  = (uint32_t)__cvta_generic_to_shared(&zS[0][0][0]);
    uint32_t bcSm = (uint32_t)__cvta_generic_to_shared(&bcS[0][0][0]);

    // roles: tid<128 -> de chunk, tid>=128 -> z chunk (64 rows x 2 x 16B each);
    // bc: every thread one chunk (64 rows x 4 x 16B)
    const int isZ = (tid >= 128);
    const int dr  = (tid & 127) >> 1;      // row 0..63
    const int dp  = (tid & 1) * 8;         // half offset 0/8
    const int bcr = tid >> 2;              // row 0..63
    const int bcp = (tid & 3) * 8;         // half offset

    auto loadChunk = [&](int c, int buf) {
        int s = br ? (Ss - 1 - (c * SCH + dr)) : (c * SCH + dr);
        if (!isZ) {
            const __half* gd = de + (rowBase + s) * Ee + e0 + dp;
            CP16F(deSm + (uint32_t)((buf * SCH + dr) * 16 + dp) * 2u, gd);
        } else {
            const __half* gz = z + (rowBase + s) * (size_t)ldz + e0 + dp;
            CP16F(zSm + (uint32_t)((buf * SCH + dr) * 16 + dp) * 2u, gz);
        }
        int s0 = br ? (Ss - 1 - (c * SCH + bcr)) : (c * SCH + bcr);
        const __half* g0 = dbc + (rowBase + s0) * DBCW + Rr + bcp;
        CP16F(bcSm + (uint32_t)((buf * SCH + bcr) * 32 + bcp) * 2u, g0);
    };

    loadChunk(0, 0);
    asm volatile("cp.async.commit_group;");

    float h = 0.0f;

    for (int c = 0; c < NCH; c++) {
        if (c + 1 < NCH) {
            loadChunk(c + 1, (c + 1) & 1);
            asm volatile("cp.async.commit_group;");
            asm volatile("cp.async.wait_group 1;");
        } else {
            asm volatile("cp.async.wait_group 0;");
        }
        __syncthreads();

        const int buf = c & 1;
#pragma unroll 8
        for (int cs = 0; cs < SCH; cs++) {
            float dlt = __half2float(deS[buf][cs][u]);
            float uu  = __half2float(zS[buf][cs][u]);
            float Bv  = __half2float(bcS[buf][cs][n]);
            float Cv  = __half2float(bcS[buf][cs][16 + n]);

            h = __expf(dlt * A_n) * h + dlt * Bv * uu;
            float y = h * Cv;
            y += __shfl_xor_sync(0xffffffffu, y, 8);
            y += __shfl_xor_sync(0xffffffffu, y, 4);
            y += __shfl_xor_sync(0xffffffffu, y, 2);
            y += __shfl_xor_sync(0xffffffffu, y, 1);
            if (n == 0) ggS[cs][u] = y + uu * Dp_e;
        }
        __syncthreads();

        {
            int r = tid >> 2, p = (tid & 3) * 4;
            int s = br ? (Ss - 1 - (c * SCH + r)) : (c * SCH + r);
            *(float4*)&gg[(rowBase + s) * Ee + e0 + p] = *(float4*)&ggS[r][p];
        }
    }
}

// ---------------- acmb = silu(mx) * (gg1 + gg2) -> fp16 ---------------------------
__global__ void combine_kernel(const __half2* __restrict__ mzx,
                               const float4* __restrict__ gg1,
                               const float4* __restrict__ gg2,
                               __half2* __restrict__ a, int n4)
{
    int i = blockIdx.x * blockDim.x + threadIdx.x;
    if (i < n4) {
        int row  = i >> 9;              // / (Ee/4)
        int col4 = i & 511;
        // mx half of mzx: row stride 2048 half2, mx offset 1024 half2
        __half2 m0 = mzx[row * 2048 + 1024 + col4 * 2];
        __half2 m1 = mzx[row * 2048 + 1024 + col4 * 2 + 1];
        float2 f0 = __half22float2(m0), f1 = __half22float2(m1);
        float4 p = gg1[i], q = gg2[i];
        float r0 = siluf(f0.x) * (p.x + q.x);
        float r1 = siluf(f0.y) * (p.y + q.y);
        float r2 = siluf(f1.x) * (p.z + q.z);
        float r3 = siluf(f1.y) * (p.w + q.w);
        a[i * 2]     = __floats2half2_rn(r0, r1);
        a[i * 2 + 1] = __floats2half2_rn(r2, r3);
    }
}

// ---------------- host launcher ----------------------------------------------------
extern "C" void kernel_launch(void* const* d_in, const int* in_sizes, int n_in,
                              void* d_out, int out_size)
{
    const float* x     = (const float*)d_in[0];
    const float* c     = (const float*)d_in[1];
    const float* n1g   = (const float*)d_in[3];
    const float* n1b   = (const float*)d_in[4];
    const float* n2g   = (const float*)d_in[5];
    const float* n2b   = (const float*)d_in[6];
    const float* Wx    = (const float*)d_in[7];
    const float* bx    = (const float*)d_in[8];
    const float* Wz    = (const float*)d_in[9];
    const float* bz    = (const float*)d_in[10];
    const float* Wf    = (const float*)d_in[11];
    const float* bf    = (const float*)d_in[12];
    const float* Wada  = (const float*)d_in[13];
    const float* bada  = (const float*)d_in[14];
    const float* Wc1   = (const float*)d_in[15];
    const float* bc1   = (const float*)d_in[16];
    const float* Wc2   = (const float*)d_in[17];
    const float* bc2   = (const float*)d_in[18];
    const float* Wdbc1 = (const float*)d_in[19];
    const float* Wdt1  = (const float*)d_in[20];
    const float* bdt1  = (const float*)d_in[21];
    const float* Alog1 = (const float*)d_in[22];
    const float* Dp1   = (const float*)d_in[23];
    const float* Wdbc2 = (const float*)d_in[24];
    const float* Wdt2  = (const float*)d_in[25];
    const float* bdt2  = (const float*)d_in[26];
    const float* Alog2 = (const float*)d_in[27];
    const float* Dp2   = (const float*)d_in[28];
    float* out = (float*)d_out;

    float  *ada, *skip, *gg1, *gg2, *part, *bzx, *bc12;
    __half *xn, *mzx, *z12, *dbc1, *dbc2, *de1, *de2, *acmb;
    __half *wzx, *wc12, *wdbc1, *wdbc2, *wdt1, *wdt2, *wf;
    cudaGetSymbolAddress((void**)&ada,  g_ada);
    cudaGetSymbolAddress((void**)&skip, g_skip);
    cudaGetSymbolAddress((void**)&xn,   g_xn);
    cudaGetSymbolAddress((void**)&mzx,  g_mzx);
    cudaGetSymbolAddress((void**)&z12,  g_z12);
    cudaGetSymbolAddress((void**)&dbc1, g_dbc1);
    cudaGetSymbolAddress((void**)&dbc2, g_dbc2);
    cudaGetSymbolAddress((void**)&de1,  g_del1);
    cudaGetSymbolAddress((void**)&de2,  g_del2);
    cudaGetSymbolAddress((void**)&gg1,  g_gg1);
    cudaGetSymbolAddress((void**)&gg2,  g_gg2);
    cudaGetSymbolAddress((void**)&acmb, g_acmb);
    cudaGetSymbolAddress((void**)&part, g_part);
    cudaGetSymbolAddress((void**)&wzx,   g_wzx);
    cudaGetSymbolAddress((void**)&wc12,  g_wc12);
    cudaGetSymbolAddress((void**)&wdbc1, g_wdbc1);
    cudaGetSymbolAddress((void**)&wdbc2, g_wdbc2);
    cudaGetSymbolAddress((void**)&wdt1,  g_wdt1);
    cudaGetSymbolAddress((void**)&wdt2,  g_wdt2);
    cudaGetSymbolAddress((void**)&wf,    g_wf);
    cudaGetSymbolAddress((void**)&bzx,   g_bzx);
    cudaGetSymbolAddress((void**)&bc12,  g_bc12);

    const int SMEM = 49152;   // 3 stages x (8KB A + 8KB B)
    cudaFuncSetAttribute(gemm_f16<0,1>, cudaFuncAttributeMaxDynamicSharedMemorySize, SMEM);
    cudaFuncSetAttribute(gemm_f16<0,0>, cudaFuncAttributeMaxDynamicSharedMemorySize, SMEM);
    cudaFuncSetAttribute(gemm_f16<1,1>, cudaFuncAttributeMaxDynamicSharedMemorySize, SMEM);
    cudaFuncSetAttribute(gemm_f16<3,0>, cudaFuncAttributeMaxDynamicSharedMemorySize, SMEM);

    // 1. fused weight convert + bias concat (one launch)
    {
        CvtJobs jb;
        const float* srcs[NSEG] = { Wz, Wx, Wc1, Wc2, Wdbc1, Wdbc2, Wdt1, Wdt2, Wf,
                                    bz, bx, bc1, bc2 };
        void* dsts[NSEG] = { wzx, wzx + (size_t)Ee * Dd,
                             wc12, wc12 + (size_t)Ee * Ee,
                             wdbc1, wdbc2, wdt1, wdt2, wf,
                             bzx, bzx + Ee, bc12, bc12 + Ee };
        int sizes4[NSEG] = { Ee * Dd / 4, Ee * Dd / 4, Ee * Ee / 4, Ee * Ee / 4,
                             DBCW * Ee / 4, DBCW * Ee / 4, Ee * Rr / 4, Ee * Rr / 4,
                             Dd * Ee / 4, Ee / 4, Ee / 4, Ee / 4, Ee / 4 };
        int cvts[NSEG] = { 1,1,1,1,1,1,1,1,1, 0,0,0,0 };
        int off = 0;
        for (int s = 0; s < NSEG; s++) {
            jb.src[s] = (const float4*)srcs[s];
            jb.dst[s] = dsts[s];
            jb.off[s] = off;
            jb.cvt[s] = cvts[s];
            off += sizes4[s];
        }
        jb.off[NSEG] = off;
        cvt_all_kernel<<<(off + 255) / 256, 256>>>(jb, off);
    }

    // 2. ada = silu(c) @ Wada^T + bada
    ada_kernel<<<384, 256>>>(c, Wada, bada, ada);

    // 3. LN1 + modulate (-> skip fp32) + LN2 (-> xn fp16)
    ln_mod_kernel<<<BSr, 256>>>(x, n1g, n1b, n2g, n2b, ada, skip, xn);

    // 4. merged mz|mx  [2048, 4096] K=1024  (fp16 out)
    gemm_f16<0,1><<<dim3(2 * Ee / 128, BSr / 128, 1), 256, SMEM>>>(
        xn, Dd, wzx, Dd, bzx, mzx, 2 * Ee, BSr, 2 * Ee, Dd, 1, 0,
        nullptr, nullptr, nullptr, nullptr, nullptr, nullptr, nullptr);

    // 5. merged z1|z2  [2048, 4096] K=2048 (A = mz half of mzx, lda=4096)
    gemm_f16<0,1><<<dim3(2 * Ee / 128, BSr / 128, 1), 256, SMEM>>>(
        mzx, 2 * Ee, wc12, Ee, bc12, z12, 2 * Ee, BSr, 2 * Ee, Ee, 1, 0,
        nullptr, nullptr, nullptr, nullptr, nullptr, nullptr, nullptr);

    // 6. dbc (both branches, split-K=8, grid.z = 16; fp32 partials)
    gemm_f16<0,0><<<dim3(1, BSr / 128, 2 * KSPLIT), 256, SMEM>>>(
        z12, 2 * Ee, wdbc1, Ee, nullptr, part, DBCW, BSr, DBCW, Ee,
        KSPLIT, BSr * DBCW,
        z12 + Ee, wdbc2, nullptr, nullptr, nullptr, nullptr, nullptr);

    // 7. reduce both branches -> dbc1, dbc2 (fp16)
    reduce_splitk2<<<(2 * BSr * DBCW + 255) / 256, 256>>>(part, dbc1, dbc2, BSr * DBCW);

    // 8. delta (both branches, grid.z = 2), softplus, fp16 out
    gemm_f16<1,1><<<dim3(Ee / 128, BSr / 128, 2), 256, SMEM>>>(
        dbc1, DBCW, wdt1, Rr, bdt1, de1, Ee, BSr, Ee, Rr, 1, 0,
        dbc2, wdt2, bdt2, de2, nullptr, nullptr, nullptr);

    // 9. both selective scans, SMEM-staged (fp16 inputs, fp32 gg out)
    scan_smem_kernel<<<512, 256>>>(de1, de2, z12, 2 * Ee, dbc1, dbc2,
                                   Alog1, Alog2, Dp1, Dp2, gg1, gg2);

    // 10. acmb = silu(mx) * (gg1 + gg2) -> fp16
    combine_kernel<<<(BSr * Ee / 4 + 255) / 256, 256>>>(
        (const __half2*)mzx, (const float4*)gg1, (const float4*)gg2,
        (__half2*)acmb, BSr * Ee / 4);

    // 11. fused final GEMM: out = x + gate * (acmb @ Wf^T + bf + skip), fp32 out
    gemm_f16<3,0><<<dim3(Dd / 128, BSr / 128, 1), 256, SMEM>>>(
        acmb, Ee, wf, Ee, bf, out, Dd, BSr, Dd, Ee, 1, 0,
        nullptr, nullptr, nullptr, nullptr, x, skip, ada);
}

// round 14
// speedup vs baseline: 1.3861x; 1.0091x over previous
#include <cuda_runtime.h>
#include <cuda_fp16.h>
#include <math.h>
#include <stdint.h>

// Problem constants
#define Bb   2
#define Ss   1024
#define Dd   1024
#define Ee   2048
#define Nn   16
#define Rr   64
#define BSr  (Bb * Ss)          // 2048 rows
#define DBCW (Rr + 2 * Nn)      // 96
#define THREED (3 * Dd)         // 3072
#define KSPLIT 8
#define SCH  64                 // scan chunk (steps per SMEM stage)
#define NCH  (Ss / SCH)         // 16 chunks

// ---------------- scratch (device globals; no allocation in kernel_launch) ----
__device__ float  g_ada  [Bb * THREED];
__device__ float  g_skip [BSr * Dd];
__device__ __half g_xn   [BSr * Dd];
__device__ __half g_mzx  [BSr * 2 * Ee];     // mz | mx  (ld = 4096 halves)
__device__ __half g_z12  [BSr * 2 * Ee];     // z1 | z2  (ld = 4096 halves)
__device__ __half g_dbc1 [BSr * DBCW];
__device__ __half g_dbc2 [BSr * DBCW];
__device__ __half g_del1 [BSr * Ee];
__device__ __half g_del2 [BSr * Ee];
__device__ __half g_gg1  [BSr * Ee];
__device__ __half g_gg2  [BSr * Ee];
__device__ __half g_acmb [BSr * Ee];
__device__ float  g_part [2 * KSPLIT * BSr * DBCW];
// fp16 weights / fp32 concat biases
__device__ __half g_wzx  [2 * Ee * Dd];      // [Wz ; Wx]
__device__ __half g_wc12 [2 * Ee * Ee];      // [Wc1 ; Wc2]
__device__ __half g_wdbc1[DBCW * Ee];
__device__ __half g_wdbc2[DBCW * Ee];
__device__ __half g_wdt1 [Ee * Rr];
__device__ __half g_wdt2 [Ee * Rr];
__device__ __half g_wf   [Dd * Ee];
__device__ float  g_bzx  [2 * Ee];           // [bz ; bx]
__device__ float  g_bc12 [2 * Ee];           // [bc1 ; bc2]

// ---------------- helpers -----------------------------------------------------
__device__ __forceinline__ float siluf(float v) { return v / (1.0f + __expf(-v)); }
__device__ __forceinline__ float softplusf(float v) {
    return (v > 20.0f) ? v : log1pf(__expf(v));
}
__device__ __forceinline__ void mma_f16(float* c, const uint32_t* a, const uint32_t* b) {
    asm volatile(
        "mma.sync.aligned.m16n8k16.row.col.f32.f16.f16.f32 "
        "{%0,%1,%2,%3},{%4,%5,%6,%7},{%8,%9},{%0,%1,%2,%3};"
        : "+f"(c[0]), "+f"(c[1]), "+f"(c[2]), "+f"(c[3])
        : "r"(a[0]), "r"(a[1]), "r"(a[2]), "r"(a[3]), "r"(b[0]), "r"(b[1]));
}
__device__ __forceinline__ void ldsm_x4(uint32_t* r, uint32_t addr) {
    asm volatile(
        "ldmatrix.sync.aligned.m8n8.x4.shared.b16 {%0,%1,%2,%3}, [%4];"
        : "=r"(r[0]), "=r"(r[1]), "=r"(r[2]), "=r"(r[3]) : "r"(addr));
}
#define CP16(dst, src, sz) \
    asm volatile("cp.async.cg.shared.global [%0], [%1], 16, %2;" \
                 :: "r"(dst), "l"(src), "r"(sz))
#define CP16F(dst, src) \
    asm volatile("cp.async.cg.shared.global [%0], [%1], 16;" \
                 :: "r"(dst), "l"(src))

__device__ __forceinline__ float blockReduceSum(float v, float* sh) {
    int lane = threadIdx.x & 31, wid = threadIdx.x >> 5;
#pragma unroll
    for (int o = 16; o; o >>= 1) v += __shfl_xor_sync(0xffffffffu, v, o);
    __syncthreads();
    if (lane == 0) sh[wid] = v;
    __syncthreads();
    if (wid == 0) {
        v = (lane < 8) ? sh[lane] : 0.0f;
#pragma unroll
        for (int o = 4; o; o >>= 1) v += __shfl_xor_sync(0xffffffffu, v, o);
        if (lane == 0) sh[0] = v;
    }
    __syncthreads();
    return sh[0];
}

// ---------------- fused weight convert (fp32->fp16) + bias concat ---------------
#define NSEG 13
struct CvtJobs {
    const float4* src[NSEG];
    void*         dst[NSEG];
    int           off[NSEG + 1];
    int           cvt[NSEG];
};

__global__ void cvt_all_kernel(CvtJobs jb, int total4) {
    int i = blockIdx.x * blockDim.x + threadIdx.x;
    if (i >= total4) return;
    int s = 0;
#pragma unroll
    for (int k = 1; k < NSEG; k++) if (i >= jb.off[k]) s = k;
    int j = i - jb.off[s];
    float4 v = jb.src[s][j];
    if (jb.cvt[s]) {
        __half2 h0 = __floats2half2_rn(v.x, v.y);
        __half2 h1 = __floats2half2_rn(v.z, v.w);
        uint2 u = make_uint2(*(uint32_t*)&h0, *(uint32_t*)&h1);
        *(uint2*)((char*)jb.dst[s] + (size_t)j * 8) = u;
    } else {
        ((float4*)jb.dst[s])[j] = v;
    }
}

// ---------------- fp16 tensor-core GEMM (ldmatrix fragments) --------------------
// C[M,N] = A[M,K] * W[N,K]^T (+bias, +epi). Tile 128x128x32, 256 threads,
// 8 warps (2x4), warp tile 64x32, mma m16n8k16 f16 (fp32 accum). 3-stage
// cp.async pipeline, issue-before-wait, XOR-swizzled half SMEM, LDSM.x4 loads.
// EPI: 0 none, 1 softplus, 3 fused ViM final. HOUT: 1 = fp16 output, 0 = fp32.
template <int EPI, int HOUT>
__global__ __launch_bounds__(256, 2) void gemm_f16(
    const __half* __restrict__ A_, int lda,
    const __half* __restrict__ W_, int ldb,
    const float* __restrict__ bias_,
    void* __restrict__ C_, int ldc,
    int M, int N, int K, int splitK, int partStride,
    const __half* A2, const __half* W2, const float* bias2, void* C2,
    const float* xP, const float* skipP, const float* adaP)
{
    extern __shared__ __half smh[];
    __half* As = smh;             // [3][128*32] halves (8KB/stage)
    __half* Bs = smh + 12288;

    const __half* A = A_;
    const __half* W = W_;
    const float* bias = bias_;
    void* C = C_;

    const int bz = blockIdx.z;
    const int br = bz / splitK;
    const int kz = bz % splitK;
    if (br == 1) { A = A2; W = W2; bias = bias2; if (C2) C = C2; }

    const int tid  = threadIdx.x;
    const int wid  = tid >> 5, lane = tid & 31;
    const int wm   = wid >> 2, wn = wid & 3;
    const int grp  = lane >> 2, tig = lane & 3;
    const int bm   = blockIdx.y * 128, bn = blockIdx.x * 128;
    const int klen   = K / splitK;
    const int kstart = kz * klen;
    const int ntile  = klen >> 5;

    float acc[4][4][4];
#pragma unroll
    for (int i = 0; i < 4; i++)
#pragma unroll
        for (int j = 0; j < 4; j++)
#pragma unroll
            for (int r = 0; r < 4; r++) acc[i][j][r] = 0.0f;

    // cp.async roles
    uint32_t aSm[2], bSm[2], bSz[2];
    const __half* aP[2];
    const __half* bP[2];
    const uint32_t sA = (uint32_t)__cvta_generic_to_shared(As);
    const uint32_t sB = (uint32_t)__cvta_generic_to_shared(Bs);
#pragma unroll
    for (int i = 0; i < 2; i++) {
        int f = tid + i * 256;
        int m = f >> 2, cch = f & 3;
        int csw = cch ^ ((m >> 1) & 3);
        aSm[i] = sA + (uint32_t)(m * 64 + csw * 16);
        bSm[i] = sB + (uint32_t)(m * 64 + csw * 16);
        aP[i]  = A + (size_t)(bm + m) * lda + kstart + cch * 8;
        int brow = bn + m;
        bSz[i] = (brow < N) ? 16u : 0u;
        if (brow >= N) brow = N - 1;
        bP[i]  = W + (size_t)brow * ldb + kstart + cch * 8;
    }

    // ldmatrix per-lane row bases (byte offsets within a stage) + swizzle keys
    // A: lanes 0-7 m0(rows lo, chunk lo), 8-15 m1(rows hi, chunk lo),
    //    16-23 m2(rows lo, chunk hi), 24-31 m3(rows hi, chunk hi)
    const int aRowIn = (lane & 7) + ((lane >> 3) & 1) * 8;   // 0..15
    const int aCb    = lane >> 4;                            // chunk bit
    uint32_t aRowOff[4]; int aSw[4];
#pragma unroll
    for (int mt = 0; mt < 4; mt++) {
        int row = wm * 64 + mt * 16 + aRowIn;
        aRowOff[mt] = (uint32_t)(row * 64);
        aSw[mt] = (row >> 1) & 3;
    }
    // B: lanes 0-7 m0(n lo, k lo), 8-15 m1(n lo, k hi),
    //    16-23 m2(n hi, k lo), 24-31 m3(n hi, k hi)
    const int bRowIn = (lane & 7) + (lane >> 4) * 8;         // 0..15
    const int bCb    = (lane >> 3) & 1;
    uint32_t bRowOff[2]; int bSw2[2];
#pragma unroll
    for (int p = 0; p < 2; p++) {
        int n = wn * 32 + p * 16 + bRowIn;
        bRowOff[p] = (uint32_t)(n * 64);
        bSw2[p] = (n >> 1) & 3;
    }

    // prologue: stages 0 and 1
#pragma unroll
    for (int st = 0; st < 2; st++) {
        if (st < ntile) {
            const uint32_t so = (uint32_t)st * 8192u;
#pragma unroll
            for (int i = 0; i < 2; i++) {
                CP16(aSm[i] + so, aP[i], 16u);
                CP16(bSm[i] + so, bP[i], bSz[i]);
                aP[i] += 32; bP[i] += 32;
            }
            asm volatile("cp.async.commit_group;");
        }
    }

    for (int t = 0; t < ntile; t++) {
        if (t + 2 < ntile) {
            const int st = (t + 2) % 3;
            const uint32_t so = (uint32_t)st * 8192u;
#pragma unroll
            for (int i = 0; i < 2; i++) {
                CP16(aSm[i] + so, aP[i], 16u);
                CP16(bSm[i] + so, bP[i], bSz[i]);
                aP[i] += 32; bP[i] += 32;
            }
            asm volatile("cp.async.commit_group;");
            asm volatile("cp.async.wait_group 2;");
        } else if (t + 1 < ntile) {
            asm volatile("cp.async.wait_group 1;");
        } else {
            asm volatile("cp.async.wait_group 0;");
        }
        __syncthreads();

        const uint32_t stA = sA + (uint32_t)(t % 3) * 8192u;
        const uint32_t stB = sB + (uint32_t)(t % 3) * 8192u;
#pragma unroll
        for (int ks = 0; ks < 2; ks++) {
            const int cbase = ks * 2;
            uint32_t af[4][4], bf[4][2];
#pragma unroll
            for (int mt = 0; mt < 4; mt++) {
                uint32_t addr = stA + aRowOff[mt]
                              + (uint32_t)(((cbase + aCb) ^ aSw[mt]) << 4);
                ldsm_x4(af[mt], addr);
            }
#pragma unroll
            for (int p = 0; p < 2; p++) {
                uint32_t tmp[4];
                uint32_t addr = stB + bRowOff[p]
                              + (uint32_t)(((cbase + bCb) ^ bSw2[p]) << 4);
                ldsm_x4(tmp, addr);
                bf[p * 2][0]     = tmp[0];
                bf[p * 2][1]     = tmp[1];
                bf[p * 2 + 1][0] = tmp[2];
                bf[p * 2 + 1][1] = tmp[3];
            }
#pragma unroll
            for (int mt = 0; mt < 4; mt++)
#pragma unroll
                for (int nt = 0; nt < 4; nt++)
                    mma_f16(acc[mt][nt], af[mt], bf[nt]);
        }
        __syncthreads();
    }

    const bool doBias = (bias != nullptr) && (splitK == 1);
#pragma unroll
    for (int mt = 0; mt < 4; mt++) {
#pragma unroll
        for (int nt = 0; nt < 4; nt++) {
            int row = bm + wm * 64 + mt * 16 + grp;
            int col = bn + wn * 32 + nt * 8 + tig * 2;
            if (col >= N) continue;
            float b0 = doBias ? __ldg(bias + col) : 0.0f;
            float b1 = doBias ? __ldg(bias + col + 1) : 0.0f;
            float v0 = acc[mt][nt][0] + b0, v1 = acc[mt][nt][1] + b1;
            float v2 = acc[mt][nt][2] + b0, v3 = acc[mt][nt][3] + b1;
            if (EPI == 1) {
                v0 = softplusf(v0); v1 = softplusf(v1);
                v2 = softplusf(v2); v3 = softplusf(v3);
            } else if (EPI == 3) {
                int bb = row >> 10;
                float g0 = __ldg(adaP + bb * THREED + 2 * Dd + col);
                float g1 = __ldg(adaP + bb * THREED + 2 * Dd + col + 1);
                size_t i0 = (size_t)row * Dd + col;
                size_t i1 = (size_t)(row + 8) * Dd + col;
                v0 = __ldg(xP + i0)     + g0 * (v0 + __ldg(skipP + i0));
                v1 = __ldg(xP + i0 + 1) + g1 * (v1 + __ldg(skipP + i0 + 1));
                v2 = __ldg(xP + i1)     + g0 * (v2 + __ldg(skipP + i1));
                v3 = __ldg(xP + i1 + 1) + g1 * (v3 + __ldg(skipP + i1 + 1));
            }
            if (HOUT) {
                __half* Ch = (__half*)C + (size_t)bz * partStride;
                *(__half2*)&Ch[(size_t)row * ldc + col] = __floats2half2_rn(v0, v1);
                *(__half2*)&Ch[(size_t)(row + 8) * ldc + col] = __floats2half2_rn(v2, v3);
            } else {
                float* Cf = (float*)C + (size_t)bz * partStride;
                *(float2*)&Cf[(size_t)row * ldc + col] = make_float2(v0, v1);
                *(float2*)&Cf[(size_t)(row + 8) * ldc + col] = make_float2(v2, v3);
            }
        }
    }
}

// ---------------- split-K reduction (fp32 partials -> fp16 out) ------------------
__global__ void reduce_splitk2(const float* __restrict__ part,
                               __half* __restrict__ out1,
                               __half* __restrict__ out2, int n)
{
    int i = blockIdx.x * blockDim.x + threadIdx.x;
    if (i < 2 * n) {
        int br = (i >= n);
        int j  = i - br * n;
        const float* p = part + (size_t)(br * KSPLIT) * n + j;
        float s = 0.0f;
#pragma unroll
        for (int z = 0; z < KSPLIT; z++) s += p[(size_t)z * n];
        __half v = __float2half_rn(s);
        if (br) out2[j] = v; else out1[j] = v;
    }
}

// ---------------- ada: one warp computes both batch outputs ----------------------
__global__ __launch_bounds__(256) void ada_kernel(
    const float* __restrict__ c, const float* __restrict__ Wada,
    const float* __restrict__ bada, float* __restrict__ ada)
{
    int w    = (blockIdx.x * blockDim.x + threadIdx.x) >> 5;   // 0..3071
    int lane = threadIdx.x & 31;

    const float4* wp  = (const float4*)(Wada + (size_t)w * 2 * Dd);
    const float4* c0p = (const float4*)c;
    const float4* c1p = (const float4*)(c + 2 * Dd);
    float s0 = 0.0f, s1 = 0.0f;
#pragma unroll
    for (int it = 0; it < 16; it++) {
        float4 wv = __ldg(&wp[lane + it * 32]);
        float4 a0 = __ldg(&c0p[lane + it * 32]);
        float4 a1 = __ldg(&c1p[lane + it * 32]);
        s0 += siluf(a0.x) * wv.x + siluf(a0.y) * wv.y
            + siluf(a0.z) * wv.z + siluf(a0.w) * wv.w;
        s1 += siluf(a1.x) * wv.x + siluf(a1.y) * wv.y
            + siluf(a1.z) * wv.z + siluf(a1.w) * wv.w;
    }
#pragma unroll
    for (int off = 16; off; off >>= 1) {
        s0 += __shfl_xor_sync(0xffffffffu, s0, off);
        s1 += __shfl_xor_sync(0xffffffffu, s1, off);
    }
    if (lane == 0) {
        float bv = __ldg(bada + w);
        ada[w] = s0 + bv;
        ada[THREED + w] = s1 + bv;
    }
}

// ---------------- fused LN1 + modulate(+store skip) + LN2 (xn -> fp16) -----------
__global__ __launch_bounds__(256) void ln_mod_kernel(
    const float* __restrict__ x,
    const float* __restrict__ g1, const float* __restrict__ b1,
    const float* __restrict__ g2, const float* __restrict__ b2,
    const float* __restrict__ ada,
    float* __restrict__ skip, __half* __restrict__ xn)
{
    __shared__ float sh[8];
    const int row = blockIdx.x;
    const int b = row >> 10;
    const float* xr = x + (size_t)row * Dd;

    float v[4];
#pragma unroll
    for (int j = 0; j < 4; j++) v[j] = xr[threadIdx.x + j * 256];

    float s1 = 0.0f, s2 = 0.0f;
#pragma unroll
    for (int j = 0; j < 4; j++) { s1 += v[j]; s2 += v[j] * v[j]; }
    s1 = blockReduceSum(s1, sh);
    s2 = blockReduceSum(s2, sh);
    float m  = s1 * (1.0f / Dd);
    float rs = rsqrtf(s2 * (1.0f / Dd) - m * m + 1e-5f);

    float t[4];
    s1 = 0.0f; s2 = 0.0f;
#pragma unroll
    for (int j = 0; j < 4; j++) {
        int d = threadIdx.x + j * 256;
        float tt = (v[j] - m) * rs * g1[d] + b1[d];
        tt = tt * (1.0f + ada[b * THREED + Dd + d]) + ada[b * THREED + d];
        t[j] = tt;
        skip[(size_t)row * Dd + d] = tt;
        s1 += tt; s2 += tt * tt;
    }
    s1 = blockReduceSum(s1, sh);
    s2 = blockReduceSum(s2, sh);
    float m2  = s1 * (1.0f / Dd);
    float rs2 = rsqrtf(s2 * (1.0f / Dd) - m2 * m2 + 1e-5f);

#pragma unroll
    for (int j = 0; j < 4; j++) {
        int d = threadIdx.x + j * 256;
        xn[(size_t)row * Dd + d] = __float2half_rn((t[j] - m2) * rs2 * g2[d] + b2[d]);
    }
}

// ---------------- SMEM-staged selective scan (fp16 in, fp16 gg out) ---------------
__global__ __launch_bounds__(256) void scan_smem_kernel(
    const __half* __restrict__ de1, const __half* __restrict__ de2,
    const __half* __restrict__ z12, int ldz,
    const __half* __restrict__ dbc1, const __half* __restrict__ dbc2,
    const float* __restrict__ Alog1, const float* __restrict__ Alog2,
    const float* __restrict__ Dp1, const float* __restrict__ Dp2,
    __half* __restrict__ gg1, __half* __restrict__ gg2)
{
    __shared__ __half deS[2][SCH][16];
    __shared__ __half zS [2][SCH][16];
    __shared__ __half bcS[2][SCH][32];
    __shared__ __half ggS[SCH][16];

    const int tid = threadIdx.x;
    const int u   = tid >> 4;
    const int n   = tid & 15;

    const int bx = blockIdx.x;         // 0..511
    const int et = bx & 127;
    const int b  = (bx >> 7) & 1;
    const int br = bx >> 8;
    const int e0 = et * 16;

    const __half* de   = br ? de2  : de1;
    const __half* z    = z12 + (br ? Ee : 0);
    const __half* dbc  = br ? dbc2 : dbc1;
    const float* Alog  = br ? Alog2 : Alog1;
    const float* Dp    = br ? Dp2  : Dp1;
    __half*      gg    = br ? gg2  : gg1;

    const int e = e0 + u;
    const float A_n  = -__expf(Alog[e * Nn + n]);
    const float Dp_e = Dp[e];

    const size_t rowBase = (size_t)b * Ss;

    uint32_t deSm = (uint32_t)__cvta_generic_to_shared(&deS[0][0][0]);
    uint32_t zSm  = (uint32_t)__cvta_generic_to_shared(&zS[0][0][0]);
    uint32_t bcSm = (uint32_t)__cvta_generic_to_shared(&bcS[0][0][0]);

    const int isZ = (tid >= 128);
    const int dr  = (tid & 127) >> 1;      // row 0..63
    const int dp  = (tid & 1) * 8;         // half offset 0/8
    const int bcr = tid >> 2;              // row 0..63
    const int bcp = (tid & 3) * 8;

    auto loadChunk = [&](int c, int buf) {
        int s = br ? (Ss - 1 - (c * SCH + dr)) : (c * SCH + dr);
        if (!isZ) {
            const __half* gd = de + (rowBase + s) * Ee + e0 + dp;
            CP16F(deSm + (uint32_t)((buf * SCH + dr) * 16 + dp) * 2u, gd);
        } else {
            const __half* gz = z + (rowBase + s) * (size_t)ldz + e0 + dp;
            CP16F(zSm + (uint32_t)((buf * SCH + dr) * 16 + dp) * 2u, gz);
        }
        int s0 = br ? (Ss - 1 - (c * SCH + bcr)) : (c * SCH + bcr);
        const __half* g0 = dbc + (rowBase + s0) * DBCW + Rr + bcp;
        CP16F(bcSm + (uint32_t)((buf * SCH + bcr) * 32 + bcp) * 2u, g0);
    };

    loadChunk(0, 0);
    asm volatile("cp.async.commit_group;");

    float h = 0.0f;

    for (int c = 0; c < NCH; c++) {
        if (c + 1 < NCH) {
            loadChunk(c + 1, (c + 1) & 1);
            asm volatile("cp.async.commit_group;");
            asm volatile("cp.async.wait_group 1;");
        } else {
            asm volatile("cp.async.wait_group 0;");
        }
        __syncthreads();

        const int buf = c & 1;
#pragma unroll 8
        for (int cs = 0; cs < SCH; cs++) {
            float dlt = __half2float(deS[buf][cs][u]);
            float uu  = __half2float(zS[buf][cs][u]);
            float Bv  = __half2float(bcS[buf][cs][n]);
            float Cv  = __half2float(bcS[buf][cs][16 + n]);

            h = __expf(dlt * A_n) * h + dlt * Bv * uu;
            float y = h * Cv;
            y += __shfl_xor_sync(0xffffffffu, y, 8);
            y += __shfl_xor_sync(0xffffffffu, y, 4);
            y += __shfl_xor_sync(0xffffffffu, y, 2);
            y += __shfl_xor_sync(0xffffffffu, y, 1);
            if (n == 0) ggS[cs][u] = __float2half_rn(y + uu * Dp_e);
        }
        __syncthreads();

        // flush: 128 threads x 16B (8 halves)
        if (tid < 128) {
            int r = tid >> 1, p = (tid & 1) * 8;
            int s = br ? (Ss - 1 - (c * SCH + r)) : (c * SCH + r);
            *(uint4*)&gg[(rowBase + s) * Ee + e0 + p] = *(uint4*)&ggS[r][p];
        }
    }
}

// ---------------- acmb = silu(mx) * (gg1 + gg2) -> fp16 ---------------------------
__global__ void combine_kernel(const __half2* __restrict__ mzx,
                               const __half2* __restrict__ gg1,
                               const __half2* __restrict__ gg2,
                               __half2* __restrict__ a, int n2)
{
    int i = blockIdx.x * blockDim.x + threadIdx.x;   // half2 index over [BSr*Ee/2]
    if (i < n2) {
        int row  = i >> 10;             // / (Ee/2)
        int col2 = i & 1023;
        __half2 m = mzx[row * 2048 + 1024 + col2];   // mx half (ld = 2048 half2)
        float2 fm = __half22float2(m);
        float2 p = __half22float2(gg1[i]);
        float2 q = __half22float2(gg2[i]);
        float r0 = siluf(fm.x) * (p.x + q.x);
        float r1 = siluf(fm.y) * (p.y + q.y);
        a[i] = __floats2half2_rn(r0, r1);
    }
}

// ---------------- host launcher ----------------------------------------------------
extern "C" void kernel_launch(void* const* d_in, const int* in_sizes, int n_in,
                              void* d_out, int out_size)
{
    const float* x     = (const float*)d_in[0];
    const float* c     = (const float*)d_in[1];
    const float* n1g   = (const float*)d_in[3];
    const float* n1b   = (const float*)d_in[4];
    const float* n2g   = (const float*)d_in[5];
    const float* n2b   = (const float*)d_in[6];
    const float* Wx    = (const float*)d_in[7];
    const float* bx    = (const float*)d_in[8];
    const float* Wz    = (const float*)d_in[9];
    const float* bz    = (const float*)d_in[10];
    const float* Wf    = (const float*)d_in[11];
    const float* bf    = (const float*)d_in[12];
    const float* Wada  = (const float*)d_in[13];
    const float* bada  = (const float*)d_in[14];
    const float* Wc1   = (const float*)d_in[15];
    const float* bc1   = (const float*)d_in[16];
    const float* Wc2   = (const float*)d_in[17];
    const float* bc2   = (const float*)d_in[18];
    const float* Wdbc1 = (const float*)d_in[19];
    const float* Wdt1  = (const float*)d_in[20];
    const float* bdt1  = (const float*)d_in[21];
    const float* Alog1 = (const float*)d_in[22];
    const float* Dp1   = (const float*)d_in[23];
    const float* Wdbc2 = (const float*)d_in[24];
    const float* Wdt2  = (const float*)d_in[25];
    const float* bdt2  = (const float*)d_in[26];
    const float* Alog2 = (const float*)d_in[27];
    const float* Dp2   = (const float*)d_in[28];
    float* out = (float*)d_out;

    float  *ada, *skip, *part, *bzx, *bc12;
    __half *xn, *mzx, *z12, *dbc1, *dbc2, *de1, *de2, *gg1, *gg2, *acmb;
    __half *wzx, *wc12, *wdbc1, *wdbc2, *wdt1, *wdt2, *wf;
    cudaGetSymbolAddress((void**)&ada,  g_ada);
    cudaGetSymbolAddress((void**)&skip, g_skip);
    cudaGetSymbolAddress((void**)&xn,   g_xn);
    cudaGetSymbolAddress((void**)&mzx,  g_mzx);
    cudaGetSymbolAddress((void**)&z12,  g_z12);
    cudaGetSymbolAddress((void**)&dbc1, g_dbc1);
    cudaGetSymbolAddress((void**)&dbc2, g_dbc2);
    cudaGetSymbolAddress((void**)&de1,  g_del1);
    cudaGetSymbolAddress((void**)&de2,  g_del2);
    cudaGetSymbolAddress((void**)&gg1,  g_gg1);
    cudaGetSymbolAddress((void**)&gg2,  g_gg2);
    cudaGetSymbolAddress((void**)&acmb, g_acmb);
    cudaGetSymbolAddress((void**)&part, g_part);
    cudaGetSymbolAddress((void**)&wzx,   g_wzx);
    cudaGetSymbolAddress((void**)&wc12,  g_wc12);
    cudaGetSymbolAddress((void**)&wdbc1, g_wdbc1);
    cudaGetSymbolAddress((void**)&wdbc2, g_wdbc2);
    cudaGetSymbolAddress((void**)&wdt1,  g_wdt1);
    cudaGetSymbolAddress((void**)&wdt2,  g_wdt2);
    cudaGetSymbolAddress((void**)&wf,    g_wf);
    cudaGetSymbolAddress((void**)&bzx,   g_bzx);
    cudaGetSymbolAddress((void**)&bc12,  g_bc12);

    const int SMEM = 49152;   // 3 stages x (8KB A + 8KB B)
    cudaFuncSetAttribute(gemm_f16<0,1>, cudaFuncAttributeMaxDynamicSharedMemorySize, SMEM);
    cudaFuncSetAttribute(gemm_f16<0,0>, cudaFuncAttributeMaxDynamicSharedMemorySize, SMEM);
    cudaFuncSetAttribute(gemm_f16<1,1>, cudaFuncAttributeMaxDynamicSharedMemorySize, SMEM);
    cudaFuncSetAttribute(gemm_f16<3,0>, cudaFuncAttributeMaxDynamicSharedMemorySize, SMEM);

    // 1. fused weight convert + bias concat (one launch)
    {
        CvtJobs jb;
        const float* srcs[NSEG] = { Wz, Wx, Wc1, Wc2, Wdbc1, Wdbc2, Wdt1, Wdt2, Wf,
                                    bz, bx, bc1, bc2 };
        void* dsts[NSEG] = { wzx, wzx + (size_t)Ee * Dd,
                             wc12, wc12 + (size_t)Ee * Ee,
                             wdbc1, wdbc2, wdt1, wdt2, wf,
                             bzx, bzx + Ee, bc12, bc12 + Ee };
        int sizes4[NSEG] = { Ee * Dd / 4, Ee * Dd / 4, Ee * Ee / 4, Ee * Ee / 4,
                             DBCW * Ee / 4, DBCW * Ee / 4, Ee * Rr / 4, Ee * Rr / 4,
                             Dd * Ee / 4, Ee / 4, Ee / 4, Ee / 4, Ee / 4 };
        int cvts[NSEG] = { 1,1,1,1,1,1,1,1,1, 0,0,0,0 };
        int off = 0;
        for (int s = 0; s < NSEG; s++) {
            jb.src[s] = (const float4*)srcs[s];
            jb.dst[s] = dsts[s];
            jb.off[s] = off;
            jb.cvt[s] = cvts[s];
            off += sizes4[s];
        }
        jb.off[NSEG] = off;
        cvt_all_kernel<<<(off + 255) / 256, 256>>>(jb, off);
    }

    // 2. ada = silu(c) @ Wada^T + bada
    ada_kernel<<<384, 256>>>(c, Wada, bada, ada);

    // 3. LN1 + modulate (-> skip fp32) + LN2 (-> xn fp16)
    ln_mod_kernel<<<BSr, 256>>>(x, n1g, n1b, n2g, n2b, ada, skip, xn);

    // 4. merged mz|mx  [2048, 4096] K=1024  (fp16 out)
    gemm_f16<0,1><<<dim3(2 * Ee / 128, BSr / 128, 1), 256, SMEM>>>(
        xn, Dd, wzx, Dd, bzx, mzx, 2 * Ee, BSr, 2 * Ee, Dd, 1, 0,
        nullptr, nullptr, nullptr, nullptr, nullptr, nullptr, nullptr);

    // 5. merged z1|z2  [2048, 4096] K=2048 (A = mz half of mzx, lda=4096)
    gemm_f16<0,1><<<dim3(2 * Ee / 128, BSr / 128, 1), 256, SMEM>>>(
        mzx, 2 * Ee, wc12, Ee, bc12, z12, 2 * Ee, BSr, 2 * Ee, Ee, 1, 0,
        nullptr, nullptr, nullptr, nullptr, nullptr, nullptr, nullptr);

    // 6. dbc (both branches, split-K=8, grid.z = 16; fp32 partials)
    gemm_f16<0,0><<<dim3(1, BSr / 128, 2 * KSPLIT), 256, SMEM>>>(
        z12, 2 * Ee, wdbc1, Ee, nullptr, part, DBCW, BSr, DBCW, Ee,
        KSPLIT, BSr * DBCW,
        z12 + Ee, wdbc2, nullptr, nullptr, nullptr, nullptr, nullptr);

    // 7. reduce both branches -> dbc1, dbc2 (fp16)
    reduce_splitk2<<<(2 * BSr * DBCW + 255) / 256, 256>>>(part, dbc1, dbc2, BSr * DBCW);

    // 8. delta (both branches, grid.z = 2), softplus, fp16 out
    gemm_f16<1,1><<<dim3(Ee / 128, BSr / 128, 2), 256, SMEM>>>(
        dbc1, DBCW, wdt1, Rr, bdt1, de1, Ee, BSr, Ee, Rr, 1, 0,
        dbc2, wdt2, bdt2, de2, nullptr, nullptr, nullptr);

    // 9. both selective scans, SMEM-staged (fp16 in, fp16 gg out)
    scan_smem_kernel<<<512, 256>>>(de1, de2, z12, 2 * Ee, dbc1, dbc2,
                                   Alog1, Alog2, Dp1, Dp2, gg1, gg2);

    // 10. acmb = silu(mx) * (gg1 + gg2) -> fp16
    combine_kernel<<<(BSr * Ee / 2 + 255) / 256, 256>>>(
        (const __half2*)mzx, (const __half2*)gg1, (const __half2*)gg2,
        (__half2*)acmb, BSr * Ee / 2);

    // 11. fused final GEMM: out = x + gate * (acmb @ Wf^T + bf + skip), fp32 out
    gemm_f16<3,0><<<dim3(Dd / 128, BSr / 128, 1), 256, SMEM>>>(
        acmb, Ee, wf, Ee, bf, out, Dd, BSr, Dd, Ee, 1, 0,
        nullptr, nullptr, nullptr, nullptr, x, skip, ada);
}

// round 15
// speedup vs baseline: 1.4793x; 1.0672x over previous
#include <cuda_runtime.h>
#include <cuda_fp16.h>
#include <math.h>
#include <stdint.h>

// Problem constants
#define Bb   2
#define Ss   1024
#define Dd   1024
#define Ee   2048
#define Nn   16
#define Rr   64
#define BSr  (Bb * Ss)          // 2048 rows
#define DBCW (Rr + 2 * Nn)      // 96
#define THREED (3 * Dd)         // 3072
#define KSPLIT 8
#define SCH  64                 // scan chunk (steps per SMEM stage)
#define NCH  (Ss / SCH)         // 16 chunks

// ---------------- scratch (device globals; no allocation in kernel_launch) ----
__device__ float  g_ada  [Bb * THREED];
__device__ float  g_skip [BSr * Dd];
__device__ __half g_xn   [BSr * Dd];
__device__ __half g_mzx  [BSr * 2 * Ee];     // mz | mx  (ld = 4096 halves)
__device__ __half g_z12  [BSr * 2 * Ee];     // z1 | z2  (ld = 4096 halves)
__device__ __half g_dbc1 [BSr * DBCW];
__device__ __half g_dbc2 [BSr * DBCW];
__device__ __half g_del1 [BSr * Ee];
__device__ __half g_del2 [BSr * Ee];
__device__ __half g_gg1  [BSr * Ee];
__device__ __half g_gg2  [BSr * Ee];
__device__ __half g_acmb [BSr * Ee];
__device__ float  g_part [2 * KSPLIT * BSr * DBCW];
// fp16 weights / fp32 concat biases
__device__ __half g_wzx  [2 * Ee * Dd];      // [Wz ; Wx]
__device__ __half g_wc12 [2 * Ee * Ee];      // [Wc1 ; Wc2]
__device__ __half g_wdbc1[DBCW * Ee];
__device__ __half g_wdbc2[DBCW * Ee];
__device__ __half g_wdt1 [Ee * Rr];
__device__ __half g_wdt2 [Ee * Rr];
__device__ __half g_wf   [Dd * Ee];
__device__ float  g_bzx  [2 * Ee];           // [bz ; bx]
__device__ float  g_bc12 [2 * Ee];           // [bc1 ; bc2]

// ---------------- helpers -----------------------------------------------------
__device__ __forceinline__ float siluf(float v) { return v / (1.0f + __expf(-v)); }
__device__ __forceinline__ float softplusf(float v) {
    return (v > 20.0f) ? v : log1pf(__expf(v));
}
__device__ __forceinline__ void mma_f16(float* c, const uint32_t* a, const uint32_t* b) {
    asm volatile(
        "mma.sync.aligned.m16n8k16.row.col.f32.f16.f16.f32 "
        "{%0,%1,%2,%3},{%4,%5,%6,%7},{%8,%9},{%0,%1,%2,%3};"
        : "+f"(c[0]), "+f"(c[1]), "+f"(c[2]), "+f"(c[3])
        : "r"(a[0]), "r"(a[1]), "r"(a[2]), "r"(a[3]), "r"(b[0]), "r"(b[1]));
}
__device__ __forceinline__ void ldsm_x4(uint32_t* r, uint32_t addr) {
    asm volatile(
        "ldmatrix.sync.aligned.m8n8.x4.shared.b16 {%0,%1,%2,%3}, [%4];"
        : "=r"(r[0]), "=r"(r[1]), "=r"(r[2]), "=r"(r[3]) : "r"(addr));
}
#define CP16(dst, src, sz) \
    asm volatile("cp.async.cg.shared.global [%0], [%1], 16, %2;" \
                 :: "r"(dst), "l"(src), "r"(sz))
#define CP16F(dst, src) \
    asm volatile("cp.async.cg.shared.global [%0], [%1], 16;" \
                 :: "r"(dst), "l"(src))

__device__ __forceinline__ float blockReduceSum(float v, float* sh) {
    int lane = threadIdx.x & 31, wid = threadIdx.x >> 5;
#pragma unroll
    for (int o = 16; o; o >>= 1) v += __shfl_xor_sync(0xffffffffu, v, o);
    __syncthreads();
    if (lane == 0) sh[wid] = v;
    __syncthreads();
    if (wid == 0) {
        v = (lane < 8) ? sh[lane] : 0.0f;
#pragma unroll
        for (int o = 4; o; o >>= 1) v += __shfl_xor_sync(0xffffffffu, v, o);
        if (lane == 0) sh[0] = v;
    }
    __syncthreads();
    return sh[0];
}

// ---------------- fused weight convert (fp32->fp16) + bias concat ---------------
#define NSEG 13
struct CvtJobs {
    const float4* src[NSEG];
    void*         dst[NSEG];
    int           off[NSEG + 1];
    int           cvt[NSEG];
};

__global__ void cvt_all_kernel(CvtJobs jb, int total4) {
    int i = blockIdx.x * blockDim.x + threadIdx.x;
    if (i >= total4) return;
    int s = 0;
#pragma unroll
    for (int k = 1; k < NSEG; k++) if (i >= jb.off[k]) s = k;
    int j = i - jb.off[s];
    float4 v = jb.src[s][j];
    if (jb.cvt[s]) {
        __half2 h0 = __floats2half2_rn(v.x, v.y);
        __half2 h1 = __floats2half2_rn(v.z, v.w);
        uint2 u = make_uint2(*(uint32_t*)&h0, *(uint32_t*)&h1);
        *(uint2*)((char*)jb.dst[s] + (size_t)j * 8) = u;
    } else {
        ((float4*)jb.dst[s])[j] = v;
    }
}

// ---------------- fp16 tensor-core GEMM (KTILE=64, ldmatrix) --------------------
// C[M,N] = A[M,K] * W[N,K]^T (+bias, +epi). Tile 128x128x64, 256 threads,
// 8 warps (2x4), warp tile 64x32, mma m16n8k16 f16 (fp32 accum). 3-stage
// cp.async pipeline (16KB/operand/stage), full-128B-row XOR swizzle
// (chunk ^ (row&7)), LDSM.x4 fragment loads. ONE k-tile = 64 k (4 mma steps).
// EPI: 0 none, 1 softplus, 3 fused ViM final. HOUT: 1 = fp16 output, 0 = fp32.
// Batching: blockIdx.z in [0, splitK * nBranch); branch selects (A2,W2,bias2,C2).
template <int EPI, int HOUT>
__global__ __launch_bounds__(256, 2) void gemm_f16(
    const __half* __restrict__ A_, int lda,
    const __half* __restrict__ W_, int ldb,
    const float* __restrict__ bias_,
    void* __restrict__ C_, int ldc,
    int M, int N, int K, int splitK, int partStride,
    const __half* A2, const __half* W2, const float* bias2, void* C2,
    const float* xP, const float* skipP, const float* adaP)
{
    extern __shared__ __half smh[];
    __half* As = smh;              // [3][128*64] halves (16KB/stage)
    __half* Bs = smh + 24576;

    const __half* A = A_;
    const __half* W = W_;
    const float* bias = bias_;
    void* C = C_;

    const int bz = blockIdx.z;
    const int br = bz / splitK;
    const int kz = bz % splitK;
    if (br == 1) { A = A2; W = W2; bias = bias2; if (C2) C = C2; }

    const int tid  = threadIdx.x;
    const int wid  = tid >> 5, lane = tid & 31;
    const int wm   = wid >> 2, wn = wid & 3;
    const int grp  = lane >> 2, tig = lane & 3;
    const int bm   = blockIdx.y * 128, bn = blockIdx.x * 128;
    const int klen   = K / splitK;
    const int kstart = kz * klen;
    const int ntile  = klen >> 6;          // 64 k per tile

    float acc[4][4][4];
#pragma unroll
    for (int i = 0; i < 4; i++)
#pragma unroll
        for (int j = 0; j < 4; j++)
#pragma unroll
            for (int r = 0; r < 4; r++) acc[i][j][r] = 0.0f;

    // cp.async roles: 4 chunks/operand/thread (128 rows x 8 x 16B chunks)
    uint32_t aSm[4], bSm[4], bSz[4];
    const __half* aP[4];
    const __half* bP[4];
    const uint32_t sA = (uint32_t)__cvta_generic_to_shared(As);
    const uint32_t sB = (uint32_t)__cvta_generic_to_shared(Bs);
#pragma unroll
    for (int i = 0; i < 4; i++) {
        int f = tid + i * 256;
        int m = f >> 3, cch = f & 7;
        int csw = cch ^ (m & 7);
        aSm[i] = sA + (uint32_t)(m * 128 + csw * 16);
        bSm[i] = sB + (uint32_t)(m * 128 + csw * 16);
        aP[i]  = A + (size_t)(bm + m) * lda + kstart + cch * 8;
        int brow = bn + m;
        bSz[i] = (brow < N) ? 16u : 0u;
        if (brow >= N) brow = N - 1;
        bP[i]  = W + (size_t)brow * ldb + kstart + cch * 8;
    }

    // ldmatrix per-lane row bases + swizzle keys
    const int aRowIn = (lane & 7) + ((lane >> 3) & 1) * 8;   // 0..15
    const int aCb    = lane >> 4;                            // chunk bit
    uint32_t aRowOff[4]; int aSw[4];
#pragma unroll
    for (int mt = 0; mt < 4; mt++) {
        int row = wm * 64 + mt * 16 + aRowIn;
        aRowOff[mt] = (uint32_t)(row * 128);
        aSw[mt] = row & 7;
    }
    const int bRowIn = (lane & 7) + (lane >> 4) * 8;         // 0..15
    const int bCb    = (lane >> 3) & 1;
    uint32_t bRowOff[2]; int bSw2[2];
#pragma unroll
    for (int p = 0; p < 2; p++) {
        int n = wn * 32 + p * 16 + bRowIn;
        bRowOff[p] = (uint32_t)(n * 128);
        bSw2[p] = n & 7;
    }

    // prologue: stages 0 and 1
#pragma unroll
    for (int st = 0; st < 2; st++) {
        if (st < ntile) {
            const uint32_t so = (uint32_t)st * 16384u;
#pragma unroll
            for (int i = 0; i < 4; i++) {
                CP16(aSm[i] + so, aP[i], 16u);
                CP16(bSm[i] + so, bP[i], bSz[i]);
                aP[i] += 64; bP[i] += 64;
            }
            asm volatile("cp.async.commit_group;");
        }
    }

    for (int t = 0; t < ntile; t++) {
        if (t + 2 < ntile) {
            const int st = (t + 2) % 3;
            const uint32_t so = (uint32_t)st * 16384u;
#pragma unroll
            for (int i = 0; i < 4; i++) {
                CP16(aSm[i] + so, aP[i], 16u);
                CP16(bSm[i] + so, bP[i], bSz[i]);
                aP[i] += 64; bP[i] += 64;
            }
            asm volatile("cp.async.commit_group;");
            asm volatile("cp.async.wait_group 2;");
        } else if (t + 1 < ntile) {
            asm volatile("cp.async.wait_group 1;");
        } else {
            asm volatile("cp.async.wait_group 0;");
        }
        __syncthreads();

        const uint32_t stA = sA + (uint32_t)(t % 3) * 16384u;
        const uint32_t stB = sB + (uint32_t)(t % 3) * 16384u;
#pragma unroll
        for (int ks = 0; ks < 4; ks++) {
            const int cbase = ks * 2;
            uint32_t af[4][4], bf[4][2];
#pragma unroll
            for (int mt = 0; mt < 4; mt++) {
                uint32_t addr = stA + aRowOff[mt]
                              + (uint32_t)(((cbase + aCb) ^ aSw[mt]) << 4);
                ldsm_x4(af[mt], addr);
            }
#pragma unroll
            for (int p = 0; p < 2; p++) {
                uint32_t tmp[4];
                uint32_t addr = stB + bRowOff[p]
                              + (uint32_t)(((cbase + bCb) ^ bSw2[p]) << 4);
                ldsm_x4(tmp, addr);
                bf[p * 2][0]     = tmp[0];
                bf[p * 2][1]     = tmp[1];
                bf[p * 2 + 1][0] = tmp[2];
                bf[p * 2 + 1][1] = tmp[3];
            }
#pragma unroll
            for (int mt = 0; mt < 4; mt++)
#pragma unroll
                for (int nt = 0; nt < 4; nt++)
                    mma_f16(acc[mt][nt], af[mt], bf[nt]);
        }
        __syncthreads();
    }

    const bool doBias = (bias != nullptr) && (splitK == 1);
#pragma unroll
    for (int mt = 0; mt < 4; mt++) {
#pragma unroll
        for (int nt = 0; nt < 4; nt++) {
            int row = bm + wm * 64 + mt * 16 + grp;
            int col = bn + wn * 32 + nt * 8 + tig * 2;
            if (col >= N) continue;
            float b0 = doBias ? __ldg(bias + col) : 0.0f;
            float b1 = doBias ? __ldg(bias + col + 1) : 0.0f;
            float v0 = acc[mt][nt][0] + b0, v1 = acc[mt][nt][1] + b1;
            float v2 = acc[mt][nt][2] + b0, v3 = acc[mt][nt][3] + b1;
            if (EPI == 1) {
                v0 = softplusf(v0); v1 = softplusf(v1);
                v2 = softplusf(v2); v3 = softplusf(v3);
            } else if (EPI == 3) {
                int bb = row >> 10;
                float g0 = __ldg(adaP + bb * THREED + 2 * Dd + col);
                float g1 = __ldg(adaP + bb * THREED + 2 * Dd + col + 1);
                size_t i0 = (size_t)row * Dd + col;
                size_t i1 = (size_t)(row + 8) * Dd + col;
                v0 = __ldg(xP + i0)     + g0 * (v0 + __ldg(skipP + i0));
                v1 = __ldg(xP + i0 + 1) + g1 * (v1 + __ldg(skipP + i0 + 1));
                v2 = __ldg(xP + i1)     + g0 * (v2 + __ldg(skipP + i1));
                v3 = __ldg(xP + i1 + 1) + g1 * (v3 + __ldg(skipP + i1 + 1));
            }
            if (HOUT) {
                __half* Ch = (__half*)C + (size_t)bz * partStride;
                *(__half2*)&Ch[(size_t)row * ldc + col] = __floats2half2_rn(v0, v1);
                *(__half2*)&Ch[(size_t)(row + 8) * ldc + col] = __floats2half2_rn(v2, v3);
            } else {
                float* Cf = (float*)C + (size_t)bz * partStride;
                *(float2*)&Cf[(size_t)row * ldc + col] = make_float2(v0, v1);
                *(float2*)&Cf[(size_t)(row + 8) * ldc + col] = make_float2(v2, v3);
            }
        }
    }
}

// ---------------- split-K reduction (fp32 partials -> fp16 out) ------------------
__global__ void reduce_splitk2(const float* __restrict__ part,
                               __half* __restrict__ out1,
                               __half* __restrict__ out2, int n)
{
    int i = blockIdx.x * blockDim.x + threadIdx.x;
    if (i < 2 * n) {
        int br = (i >= n);
        int j  = i - br * n;
        const float* p = part + (size_t)(br * KSPLIT) * n + j;
        float s = 0.0f;
#pragma unroll
        for (int z = 0; z < KSPLIT; z++) s += p[(size_t)z * n];
        __half v = __float2half_rn(s);
        if (br) out2[j] = v; else out1[j] = v;
    }
}

// ---------------- ada: one warp computes both batch outputs ----------------------
__global__ __launch_bounds__(256) void ada_kernel(
    const float* __restrict__ c, const float* __restrict__ Wada,
    const float* __restrict__ bada, float* __restrict__ ada)
{
    int w    = (blockIdx.x * blockDim.x + threadIdx.x) >> 5;   // 0..3071
    int lane = threadIdx.x & 31;

    const float4* wp  = (const float4*)(Wada + (size_t)w * 2 * Dd);
    const float4* c0p = (const float4*)c;
    const float4* c1p = (const float4*)(c + 2 * Dd);
    float s0 = 0.0f, s1 = 0.0f;
#pragma unroll
    for (int it = 0; it < 16; it++) {
        float4 wv = __ldg(&wp[lane + it * 32]);
        float4 a0 = __ldg(&c0p[lane + it * 32]);
        float4 a1 = __ldg(&c1p[lane + it * 32]);
        s0 += siluf(a0.x) * wv.x + siluf(a0.y) * wv.y
            + siluf(a0.z) * wv.z + siluf(a0.w) * wv.w;
        s1 += siluf(a1.x) * wv.x + siluf(a1.y) * wv.y
            + siluf(a1.z) * wv.z + siluf(a1.w) * wv.w;
    }
#pragma unroll
    for (int off = 16; off; off >>= 1) {
        s0 += __shfl_xor_sync(0xffffffffu, s0, off);
        s1 += __shfl_xor_sync(0xffffffffu, s1, off);
    }
    if (lane == 0) {
        float bv = __ldg(bada + w);
        ada[w] = s0 + bv;
        ada[THREED + w] = s1 + bv;
    }
}

// ---------------- fused LN1 + modulate(+store skip) + LN2 (xn -> fp16) -----------
__global__ __launch_bounds__(256) void ln_mod_kernel(
    const float* __restrict__ x,
    const float* __restrict__ g1, const float* __restrict__ b1,
    const float* __restrict__ g2, const float* __restrict__ b2,
    const float* __restrict__ ada,
    float* __restrict__ skip, __half* __restrict__ xn)
{
    __shared__ float sh[8];
    const int row = blockIdx.x;
    const int b = row >> 10;
    const float* xr = x + (size_t)row * Dd;

    float v[4];
#pragma unroll
    for (int j = 0; j < 4; j++) v[j] = xr[threadIdx.x + j * 256];

    float s1 = 0.0f, s2 = 0.0f;
#pragma unroll
    for (int j = 0; j < 4; j++) { s1 += v[j]; s2 += v[j] * v[j]; }
    s1 = blockReduceSum(s1, sh);
    s2 = blockReduceSum(s2, sh);
    float m  = s1 * (1.0f / Dd);
    float rs = rsqrtf(s2 * (1.0f / Dd) - m * m + 1e-5f);

    float t[4];
    s1 = 0.0f; s2 = 0.0f;
#pragma unroll
    for (int j = 0; j < 4; j++) {
        int d = threadIdx.x + j * 256;
        float tt = (v[j] - m) * rs * g1[d] + b1[d];
        tt = tt * (1.0f + ada[b * THREED + Dd + d]) + ada[b * THREED + d];
        t[j] = tt;
        skip[(size_t)row * Dd + d] = tt;
        s1 += tt; s2 += tt * tt;
    }
    s1 = blockReduceSum(s1, sh);
    s2 = blockReduceSum(s2, sh);
    float m2  = s1 * (1.0f / Dd);
    float rs2 = rsqrtf(s2 * (1.0f / Dd) - m2 * m2 + 1e-5f);

#pragma unroll
    for (int j = 0; j < 4; j++) {
        int d = threadIdx.x + j * 256;
        xn[(size_t)row * Dd + d] = __float2half_rn((t[j] - m2) * rs2 * g2[d] + b2[d]);
    }
}

// ---------------- SMEM-staged selective scan (fp16 in, fp16 gg out) ---------------
__global__ __launch_bounds__(256) void scan_smem_kernel(
    const __half* __restrict__ de1, const __half* __restrict__ de2,
    const __half* __restrict__ z12, int ldz,
    const __half* __restrict__ dbc1, const __half* __restrict__ dbc2,
    const float* __restrict__ Alog1, const float* __restrict__ Alog2,
    const float* __restrict__ Dp1, const float* __restrict__ Dp2,
    __half* __restrict__ gg1, __half* __restrict__ gg2)
{
    __shared__ __half deS[2][SCH][16];
    __shared__ __half zS [2][SCH][16];
    __shared__ __half bcS[2][SCH][32];
    __shared__ __half ggS[SCH][16];

    const int tid = threadIdx.x;
    const int u   = tid >> 4;
    const int n   = tid & 15;

    const int bx = blockIdx.x;         // 0..511
    const int et = bx & 127;
    const int b  = (bx >> 7) & 1;
    const int br = bx >> 8;
    const int e0 = et * 16;

    const __half* de   = br ? de2  : de1;
    const __half* z    = z12 + (br ? Ee : 0);
    const __half* dbc  = br ? dbc2 : dbc1;
    const float* Alog  = br ? Alog2 : Alog1;
    const float* Dp    = br ? Dp2  : Dp1;
    __half*      gg    = br ? gg2  : gg1;

    const int e = e0 + u;
    const float A_n  = -__expf(Alog[e * Nn + n]);
    const float Dp_e = Dp[e];

    const size_t rowBase = (size_t)b * Ss;

    uint32_t deSm = (uint32_t)__cvta_generic_to_shared(&deS[0][0][0]);
    uint32_t zSm  = (uint32_t)__cvta_generic_to_shared(&zS[0][0][0]);
    uint32_t bcSm = (uint32_t)__cvta_generic_to_shared(&bcS[0][0][0]);

    const int isZ = (tid >= 128);
    const int dr  = (tid & 127) >> 1;      // row 0..63
    const int dp  = (tid & 1) * 8;         // half offset 0/8
    const int bcr = tid >> 2;              // row 0..63
    const int bcp = (tid & 3) * 8;

    auto loadChunk = [&](int c, int buf) {
        int s = br ? (Ss - 1 - (c * SCH + dr)) : (c * SCH + dr);
        if (!isZ) {
            const __half* gd = de + (rowBase + s) * Ee + e0 + dp;
            CP16F(deSm + (uint32_t)((buf * SCH + dr) * 16 + dp) * 2u, gd);
        } else {
            const __half* gz = z + (rowBase + s) * (size_t)ldz + e0 + dp;
            CP16F(zSm + (uint32_t)((buf * SCH + dr) * 16 + dp) * 2u, gz);
        }
        int s0 = br ? (Ss - 1 - (c * SCH + bcr)) : (c * SCH + bcr);
        const __half* g0 = dbc + (rowBase + s0) * DBCW + Rr + bcp;
        CP16F(bcSm + (uint32_t)((buf * SCH + bcr) * 32 + bcp) * 2u, g0);
    };

    loadChunk(0, 0);
    asm volatile("cp.async.commit_group;");

    float h = 0.0f;

    for (int c = 0; c < NCH; c++) {
        if (c + 1 < NCH) {
            loadChunk(c + 1, (c + 1) & 1);
            asm volatile("cp.async.commit_group;");
            asm volatile("cp.async.wait_group 1;");
        } else {
            asm volatile("cp.async.wait_group 0;");
        }
        __syncthreads();

        const int buf = c & 1;
#pragma unroll 8
        for (int cs = 0; cs < SCH; cs++) {
            float dlt = __half2float(deS[buf][cs][u]);
            float uu  = __half2float(zS[buf][cs][u]);
            float Bv  = __half2float(bcS[buf][cs][n]);
            float Cv  = __half2float(bcS[buf][cs][16 + n]);

            h = __expf(dlt * A_n) * h + dlt * Bv * uu;
            float y = h * Cv;
            y += __shfl_xor_sync(0xffffffffu, y, 8);
            y += __shfl_xor_sync(0xffffffffu, y, 4);
            y += __shfl_xor_sync(0xffffffffu, y, 2);
            y += __shfl_xor_sync(0xffffffffu, y, 1);
            if (n == 0) ggS[cs][u] = __float2half_rn(y + uu * Dp_e);
        }
        __syncthreads();

        if (tid < 128) {
            int r = tid >> 1, p = (tid & 1) * 8;
            int s = br ? (Ss - 1 - (c * SCH + r)) : (c * SCH + r);
            *(uint4*)&gg[(rowBase + s) * Ee + e0 + p] = *(uint4*)&ggS[r][p];
        }
    }
}

// ---------------- acmb = silu(mx) * (gg1 + gg2) -> fp16 ---------------------------
__global__ void combine_kernel(const __half2* __restrict__ mzx,
                               const __half2* __restrict__ gg1,
                               const __half2* __restrict__ gg2,
                               __half2* __restrict__ a, int n2)
{
    int i = blockIdx.x * blockDim.x + threadIdx.x;
    if (i < n2) {
        int row  = i >> 10;             // / (Ee/2)
        int col2 = i & 1023;
        __half2 m = mzx[row * 2048 + 1024 + col2];
        float2 fm = __half22float2(m);
        float2 p = __half22float2(gg1[i]);
        float2 q = __half22float2(gg2[i]);
        float r0 = siluf(fm.x) * (p.x + q.x);
        float r1 = siluf(fm.y) * (p.y + q.y);
        a[i] = __floats2half2_rn(r0, r1);
    }
}

// ---------------- host launcher ----------------------------------------------------
extern "C" void kernel_launch(void* const* d_in, const int* in_sizes, int n_in,
                              void* d_out, int out_size)
{
    const float* x     = (const float*)d_in[0];
    const float* c     = (const float*)d_in[1];
    const float* n1g   = (const float*)d_in[3];
    const float* n1b   = (const float*)d_in[4];
    const float* n2g   = (const float*)d_in[5];
    const float* n2b   = (const float*)d_in[6];
    const float* Wx    = (const float*)d_in[7];
    const float* bx    = (const float*)d_in[8];
    const float* Wz    = (const float*)d_in[9];
    const float* bz    = (const float*)d_in[10];
    const float* Wf    = (const float*)d_in[11];
    const float* bf    = (const float*)d_in[12];
    const float* Wada  = (const float*)d_in[13];
    const float* bada  = (const float*)d_in[14];
    const float* Wc1   = (const float*)d_in[15];
    const float* bc1   = (const float*)d_in[16];
    const float* Wc2   = (const float*)d_in[17];
    const float* bc2   = (const float*)d_in[18];
    const float* Wdbc1 = (const float*)d_in[19];
    const float* Wdt1  = (const float*)d_in[20];
    const float* bdt1  = (const float*)d_in[21];
    const float* Alog1 = (const float*)d_in[22];
    const float* Dp1   = (const float*)d_in[23];
    const float* Wdbc2 = (const float*)d_in[24];
    const float* Wdt2  = (const float*)d_in[25];
    const float* bdt2  = (const float*)d_in[26];
    const float* Alog2 = (const float*)d_in[27];
    const float* Dp2   = (const float*)d_in[28];
    float* out = (float*)d_out;

    float  *ada, *skip, *part, *bzx, *bc12;
    __half *xn, *mzx, *z12, *dbc1, *dbc2, *de1, *de2, *gg1, *gg2, *acmb;
    __half *wzx, *wc12, *wdbc1, *wdbc2, *wdt1, *wdt2, *wf;
    cudaGetSymbolAddress((void**)&ada,  g_ada);
    cudaGetSymbolAddress((void**)&skip, g_skip);
    cudaGetSymbolAddress((void**)&xn,   g_xn);
    cudaGetSymbolAddress((void**)&mzx,  g_mzx);
    cudaGetSymbolAddress((void**)&z12,  g_z12);
    cudaGetSymbolAddress((void**)&dbc1, g_dbc1);
    cudaGetSymbolAddress((void**)&dbc2, g_dbc2);
    cudaGetSymbolAddress((void**)&de1,  g_del1);
    cudaGetSymbolAddress((void**)&de2,  g_del2);
    cudaGetSymbolAddress((void**)&gg1,  g_gg1);
    cudaGetSymbolAddress((void**)&gg2,  g_gg2);
    cudaGetSymbolAddress((void**)&acmb, g_acmb);
    cudaGetSymbolAddress((void**)&part, g_part);
    cudaGetSymbolAddress((void**)&wzx,   g_wzx);
    cudaGetSymbolAddress((void**)&wc12,  g_wc12);
    cudaGetSymbolAddress((void**)&wdbc1, g_wdbc1);
    cudaGetSymbolAddress((void**)&wdbc2, g_wdbc2);
    cudaGetSymbolAddress((void**)&wdt1,  g_wdt1);
    cudaGetSymbolAddress((void**)&wdt2,  g_wdt2);
    cudaGetSymbolAddress((void**)&wf,    g_wf);
    cudaGetSymbolAddress((void**)&bzx,   g_bzx);
    cudaGetSymbolAddress((void**)&bc12,  g_bc12);

    const int SMEM = 98304;   // 3 stages x (16KB A + 16KB B)
    cudaFuncSetAttribute(gemm_f16<0,1>, cudaFuncAttributeMaxDynamicSharedMemorySize, SMEM);
    cudaFuncSetAttribute(gemm_f16<0,0>, cudaFuncAttributeMaxDynamicSharedMemorySize, SMEM);
    cudaFuncSetAttribute(gemm_f16<1,1>, cudaFuncAttributeMaxDynamicSharedMemorySize, SMEM);
    cudaFuncSetAttribute(gemm_f16<3,0>, cudaFuncAttributeMaxDynamicSharedMemorySize, SMEM);

    // 1. fused weight convert + bias concat (one launch)
    {
        CvtJobs jb;
        const float* srcs[NSEG] = { Wz, Wx, Wc1, Wc2, Wdbc1, Wdbc2, Wdt1, Wdt2, Wf,
                                    bz, bx, bc1, bc2 };
        void* dsts[NSEG] = { wzx, wzx + (size_t)Ee * Dd,
                             wc12, wc12 + (size_t)Ee * Ee,
                             wdbc1, wdbc2, wdt1, wdt2, wf,
                             bzx, bzx + Ee, bc12, bc12 + Ee };
        int sizes4[NSEG] = { Ee * Dd / 4, Ee * Dd / 4, Ee * Ee / 4, Ee * Ee / 4,
                             DBCW * Ee / 4, DBCW * Ee / 4, Ee * Rr / 4, Ee * Rr / 4,
                             Dd * Ee / 4, Ee / 4, Ee / 4, Ee / 4, Ee / 4 };
        int cvts[NSEG] = { 1,1,1,1,1,1,1,1,1, 0,0,0,0 };
        int off = 0;
        for (int s = 0; s < NSEG; s++) {
            jb.src[s] = (const float4*)srcs[s];
            jb.dst[s] = dsts[s];
            jb.off[s] = off;
            jb.cvt[s] = cvts[s];
            off += sizes4[s];
        }
        jb.off[NSEG] = off;
        cvt_all_kernel<<<(off + 255) / 256, 256>>>(jb, off);
    }

    // 2. ada = silu(c) @ Wada^T + bada
    ada_kernel<<<384, 256>>>(c, Wada, bada, ada);

    // 3. LN1 + modulate (-> skip fp32) + LN2 (-> xn fp16)
    ln_mod_kernel<<<BSr, 256>>>(x, n1g, n1b, n2g, n2b, ada, skip, xn);

    // 4. merged mz|mx  [2048, 4096] K=1024  (fp16 out)
    gemm_f16<0,1><<<dim3(2 * Ee / 128, BSr / 128, 1), 256, SMEM>>>(
        xn, Dd, wzx, Dd, bzx, mzx, 2 * Ee, BSr, 2 * Ee, Dd, 1, 0,
        nullptr, nullptr, nullptr, nullptr, nullptr, nullptr, nullptr);

    // 5. merged z1|z2  [2048, 4096] K=2048 (A = mz half of mzx, lda=4096)
    gemm_f16<0,1><<<dim3(2 * Ee / 128, BSr / 128, 1), 256, SMEM>>>(
        mzx, 2 * Ee, wc12, Ee, bc12, z12, 2 * Ee, BSr, 2 * Ee, Ee, 1, 0,
        nullptr, nullptr, nullptr, nullptr, nullptr, nullptr, nullptr);

    // 6. dbc (both branches, split-K=8, grid.z = 16; fp32 partials)
    gemm_f16<0,0><<<dim3(1, BSr / 128, 2 * KSPLIT), 256, SMEM>>>(
        z12, 2 * Ee, wdbc1, Ee, nullptr, part, DBCW, BSr, DBCW, Ee,
        KSPLIT, BSr * DBCW,
        z12 + Ee, wdbc2, nullptr, nullptr, nullptr, nullptr, nullptr);

    // 7. reduce both branches -> dbc1, dbc2 (fp16)
    reduce_splitk2<<<(2 * BSr * DBCW + 255) / 256, 256>>>(part, dbc1, dbc2, BSr * DBCW);

    // 8. delta (both branches, grid.z = 2), softplus, fp16 out
    gemm_f16<1,1><<<dim3(Ee / 128, BSr / 128, 2), 256, SMEM>>>(
        dbc1, DBCW, wdt1, Rr, bdt1, de1, Ee, BSr, Ee, Rr, 1, 0,
        dbc2, wdt2, bdt2, de2, nullptr, nullptr, nullptr);

    // 9. both selective scans, SMEM-staged (fp16 in, fp16 gg out)
    scan_smem_kernel<<<512, 256>>>(de1, de2, z12, 2 * Ee, dbc1, dbc2,
                                   Alog1, Alog2, Dp1, Dp2, gg1, gg2);

    // 10. acmb = silu(mx) * (gg1 + gg2) -> fp16
    combine_kernel<<<(BSr * Ee / 2 + 255) / 256, 256>>>(
        (const __half2*)mzx, (const __half2*)gg1, (const __half2*)gg2,
        (__half2*)acmb, BSr * Ee / 2);

    // 11. fused final GEMM: out = x + gate * (acmb @ Wf^T + bf + skip), fp32 out
    gemm_f16<3,0><<<dim3(Dd / 128, BSr / 128, 1), 256, SMEM>>>(
        acmb, Ee, wf, Ee, bf, out, Dd, BSr, Dd, Ee, 1, 0,
        nullptr, nullptr, nullptr, nullptr, x, skip, ada);
}